// round 1
// baseline (speedup 1.0000x reference)
#include <cuda_runtime.h>
#include <cstdint>

#define BB 64
#define LL 1024
#define TOTAL (BB * LL)
#define VV 100000
#define DD 512
#define HH 2048
#define NHEAD 8
#define HD 64

// ---------------- scratch (static device globals; no allocation) ----------------
__device__ float g_hid[(size_t)TOTAL * HH];   // 512 MiB
__device__ float g_h  [(size_t)TOTAL * DD];   // 128 MiB
__device__ float g_k  [(size_t)TOTAL * DD];
__device__ float g_v  [(size_t)TOTAL * DD];
__device__ float g_qp [DD];
__device__ float g_ctx[BB * DD];
__device__ float g_pooled[BB * DD];
__device__ int   g_tok[TOTAL];
__device__ unsigned char g_valid[TOTAL];

// ---------------- token gather / mask ----------------
__global__ void gather_tok_kernel(const int* __restrict__ mut,
                                  const int* __restrict__ offs)
{
    int t = blockIdx.x * blockDim.x + threadIdx.x;
    if (t >= TOTAL) return;
    int b = t >> 10;         // L = 1024
    int l = t & (LL - 1);
    int s = offs[b];
    int e = offs[b + 1];
    bool ok = l < (e - s);
    g_tok[t]   = ok ? mut[s + l] : 0;
    g_valid[t] = ok ? 1 : 0;
}

// ---------------- tiled SGEMM: C[M,N] = op(gather(A) @ B + bias) ----------------
// BM=128, BN=128, BK=8, 256 threads, 8x8 microtile, smem double-buffered.
template<bool GATHER, bool RELU>
__global__ void __launch_bounds__(256, 2)
sgemm_kernel(const float* __restrict__ A, const float* __restrict__ Bm,
             const float* __restrict__ bias, float* __restrict__ C,
             int M, int N, int K, const int* __restrict__ tok)
{
    __shared__ float As[2][8][128];
    __shared__ float Bs[2][8][128];

    const int tid = threadIdx.x;
    const int bm = blockIdx.y * 128;
    const int bn = blockIdx.x * 128;

    const int a_row = tid >> 1;            // 0..127
    const int a_col = (tid & 1) << 2;      // 0 or 4
    int arow_g = bm + a_row;
    if (GATHER) arow_g = tok[arow_g];
    const float* Ap = A + (size_t)arow_g * K + a_col;

    const int b_row = tid >> 5;            // 0..7
    const int b_col = (tid & 31) << 2;     // 0..124
    const float* Bp = Bm + (size_t)b_row * N + bn + b_col;

    const int tx = tid & 15;
    const int ty = tid >> 4;

    float acc[8][8];
#pragma unroll
    for (int i = 0; i < 8; i++)
#pragma unroll
        for (int j = 0; j < 8; j++) acc[i][j] = 0.f;

    float4 af = *reinterpret_cast<const float4*>(Ap);
    float4 bf = *reinterpret_cast<const float4*>(Bp);

    int buf = 0;
    As[0][a_col + 0][a_row] = af.x;
    As[0][a_col + 1][a_row] = af.y;
    As[0][a_col + 2][a_row] = af.z;
    As[0][a_col + 3][a_row] = af.w;
    *reinterpret_cast<float4*>(&Bs[0][b_row][b_col]) = bf;
    __syncthreads();

    const int ktiles = K >> 3;
    for (int t = 0; t < ktiles; t++) {
        const bool last = (t == ktiles - 1);
        if (!last) {
            const int k0 = (t + 1) << 3;
            af = *reinterpret_cast<const float4*>(Ap + k0);
            bf = *reinterpret_cast<const float4*>(Bp + (size_t)k0 * N);
        }
#pragma unroll
        for (int kk = 0; kk < 8; kk++) {
            float4 a0 = *reinterpret_cast<const float4*>(&As[buf][kk][ty * 8]);
            float4 a1 = *reinterpret_cast<const float4*>(&As[buf][kk][ty * 8 + 4]);
            float4 b0 = *reinterpret_cast<const float4*>(&Bs[buf][kk][tx * 8]);
            float4 b1 = *reinterpret_cast<const float4*>(&Bs[buf][kk][tx * 8 + 4]);
            float ar[8] = {a0.x, a0.y, a0.z, a0.w, a1.x, a1.y, a1.z, a1.w};
            float br[8] = {b0.x, b0.y, b0.z, b0.w, b1.x, b1.y, b1.z, b1.w};
#pragma unroll
            for (int i = 0; i < 8; i++)
#pragma unroll
                for (int j = 0; j < 8; j++)
                    acc[i][j] += ar[i] * br[j];
        }
        if (!last) {
            buf ^= 1;
            As[buf][a_col + 0][a_row] = af.x;
            As[buf][a_col + 1][a_row] = af.y;
            As[buf][a_col + 2][a_row] = af.z;
            As[buf][a_col + 3][a_row] = af.w;
            *reinterpret_cast<float4*>(&Bs[buf][b_row][b_col]) = bf;
            __syncthreads();
        }
    }

    // epilogue: bias (+ReLU), vectorized store
    const float4 bia0 = *reinterpret_cast<const float4*>(&bias[bn + tx * 8]);
    const float4 bia1 = *reinterpret_cast<const float4*>(&bias[bn + tx * 8 + 4]);
#pragma unroll
    for (int i = 0; i < 8; i++) {
        const int m = bm + ty * 8 + i;
        float* Cp = C + (size_t)m * N + bn + tx * 8;
        float4 r0, r1;
        r0.x = acc[i][0] + bia0.x;  r0.y = acc[i][1] + bia0.y;
        r0.z = acc[i][2] + bia0.z;  r0.w = acc[i][3] + bia0.w;
        r1.x = acc[i][4] + bia1.x;  r1.y = acc[i][5] + bia1.y;
        r1.z = acc[i][6] + bia1.z;  r1.w = acc[i][7] + bia1.w;
        if (RELU) {
            r0.x = fmaxf(r0.x, 0.f); r0.y = fmaxf(r0.y, 0.f);
            r0.z = fmaxf(r0.z, 0.f); r0.w = fmaxf(r0.w, 0.f);
            r1.x = fmaxf(r1.x, 0.f); r1.y = fmaxf(r1.y, 0.f);
            r1.z = fmaxf(r1.z, 0.f); r1.w = fmaxf(r1.w, 0.f);
        }
        *reinterpret_cast<float4*>(Cp)     = r0;
        *reinterpret_cast<float4*>(Cp + 4) = r1;
    }
}

// ---------------- block reductions ----------------
__device__ __forceinline__ float block_sum(float v, float* red) {
#pragma unroll
    for (int o = 16; o > 0; o >>= 1) v += __shfl_xor_sync(0xffffffffu, v, o);
    const int wid = threadIdx.x >> 5, lid = threadIdx.x & 31;
    const int nw = blockDim.x >> 5;
    if (lid == 0) red[wid] = v;
    __syncthreads();
    if (wid == 0) {
        v = (lid < nw) ? red[lid] : 0.f;
#pragma unroll
        for (int o = 16; o > 0; o >>= 1) v += __shfl_xor_sync(0xffffffffu, v, o);
        if (lid == 0) red[0] = v;
    }
    __syncthreads();
    float r = red[0];
    __syncthreads();
    return r;
}

__device__ __forceinline__ float block_max(float v, float* red) {
#pragma unroll
    for (int o = 16; o > 0; o >>= 1) v = fmaxf(v, __shfl_xor_sync(0xffffffffu, v, o));
    const int wid = threadIdx.x >> 5, lid = threadIdx.x & 31;
    const int nw = blockDim.x >> 5;
    if (lid == 0) red[wid] = v;
    __syncthreads();
    if (wid == 0) {
        v = (lid < nw) ? red[lid] : -3.4e38f;
#pragma unroll
        for (int o = 16; o > 0; o >>= 1) v = fmaxf(v, __shfl_xor_sync(0xffffffffu, v, o));
        if (lid == 0) red[0] = v;
    }
    __syncthreads();
    float r = red[0];
    __syncthreads();
    return r;
}

// ---------------- qp = q @ Wq + bq ----------------
__global__ void qp_kernel(const float* __restrict__ q, const float* __restrict__ Wq,
                          const float* __restrict__ bq)
{
    __shared__ float qs[DD];
    const int j = threadIdx.x;   // 512
    qs[j] = q[j];
    __syncthreads();
    float s = bq[j];
    for (int i = 0; i < DD; i++) s += qs[i] * Wq[i * DD + j];
    g_qp[j] = s;
}

// ---------------- scores + softmax + ctx, one block per (b, h) ----------------
__global__ void attn_pool_kernel()
{
    const int bh = blockIdx.x;   // 0..511
    const int b = bh >> 3;
    const int h = bh & 7;
    const int tid = threadIdx.x; // 256

    __shared__ float qph[HD];
    __shared__ float sc[LL];
    __shared__ float red[32];
    __shared__ float part[4][HD];

    if (tid < HD) qph[tid] = g_qp[h * HD + tid];
    __syncthreads();

    const float scale = 0.125f;  // 1/sqrt(HD)
    for (int l = tid; l < LL; l += 256) {
        const float* kp = g_k + ((size_t)(b * LL + l) * DD + h * HD);
        float s = 0.f;
#pragma unroll
        for (int d = 0; d < HD; d += 4) {
            float4 kv = *reinterpret_cast<const float4*>(kp + d);
            s += qph[d] * kv.x + qph[d + 1] * kv.y + qph[d + 2] * kv.z + qph[d + 3] * kv.w;
        }
        s *= scale;
        if (!g_valid[b * LL + l]) s = -1e30f;
        sc[l] = s;
    }
    __syncthreads();

    float mx = -3.4e38f;
    for (int l = tid; l < LL; l += 256) mx = fmaxf(mx, sc[l]);
    mx = block_max(mx, red);

    float sum = 0.f;
    for (int l = tid; l < LL; l += 256) {
        float e = __expf(sc[l] - mx);
        sc[l] = e;
        sum += e;
    }
    sum = block_sum(sum, red);
    const float inv = 1.f / sum;
    __syncthreads();

    const int d = tid & 63;
    const int stripe = tid >> 6;
    float acc = 0.f;
    for (int l = stripe; l < LL; l += 4)
        acc += sc[l] * g_v[(size_t)(b * LL + l) * DD + h * HD + d];
    part[stripe][d] = acc;
    __syncthreads();
    if (tid < HD) {
        float c = (part[0][tid] + part[1][tid] + part[2][tid] + part[3][tid]) * inv;
        g_ctx[b * DD + h * HD + tid] = c;
    }
}

// ---------------- pooled = ctx @ Wo + bo ----------------
__global__ void pooled_kernel(const float* __restrict__ Wo, const float* __restrict__ bo)
{
    const int b = blockIdx.x;
    const int j = threadIdx.x;   // 512
    __shared__ float cx[DD];
    cx[j] = g_ctx[b * DD + j];
    __syncthreads();
    float s = bo[j];
    for (int i = 0; i < DD; i++) s += cx[i] * Wo[i * DD + j];
    g_pooled[b * DD + j] = s;
}

// ---------------- LayerNorm + head MLP -> logit ----------------
__global__ void head_kernel(const float* __restrict__ ln_g, const float* __restrict__ ln_b,
                            const float* __restrict__ Wh1, const float* __restrict__ bh1,
                            const float* __restrict__ Wh2, const float* __restrict__ bh2,
                            float* __restrict__ out)
{
    const int b = blockIdx.x;
    const int tid = threadIdx.x; // 256
    __shared__ float y[DD];
    __shared__ float red[32];

    float s = 0.f;
    for (int i = tid; i < DD; i += 256) s += g_pooled[b * DD + i];
    const float mu = block_sum(s, red) * (1.f / DD);

    float vs = 0.f;
    for (int i = tid; i < DD; i += 256) {
        float dd = g_pooled[b * DD + i] - mu;
        vs += dd * dd;
    }
    const float var = block_sum(vs, red) * (1.f / DD);
    const float rstd = rsqrtf(var + 1e-5f);

    for (int i = tid; i < DD; i += 256)
        y[i] = (g_pooled[b * DD + i] - mu) * rstd * ln_g[i] + ln_b[i];
    __syncthreads();

    float acc = 0.f;
    for (int j = tid; j < HH; j += 256) {
        float t = bh1[j];
        for (int i = 0; i < DD; i++) t += y[i] * Wh1[i * HH + j];
        acc += fmaxf(t, 0.f) * Wh2[j];
    }
    const float tot = block_sum(acc, red);
    if (tid == 0) out[b] = tot + bh2[0];
}

// ---------------- launcher ----------------
extern "C" void kernel_launch(void* const* d_in, const int* in_sizes, int n_in,
                              void* d_out, int out_size)
{
    const int*   mut  = (const int*)d_in[0];
    const int*   offs = (const int*)d_in[1];
    const float* emb  = (const float*)d_in[2];
    const float* W1   = (const float*)d_in[3];
    const float* b1   = (const float*)d_in[4];
    const float* W2   = (const float*)d_in[5];
    const float* b2   = (const float*)d_in[6];
    const float* q    = (const float*)d_in[7];
    const float* Wq   = (const float*)d_in[8];
    const float* bq   = (const float*)d_in[9];
    const float* Wk   = (const float*)d_in[10];
    const float* bk   = (const float*)d_in[11];
    const float* Wv   = (const float*)d_in[12];
    const float* bv   = (const float*)d_in[13];
    const float* Wo   = (const float*)d_in[14];
    const float* bo   = (const float*)d_in[15];
    const float* ln_g = (const float*)d_in[16];
    const float* ln_b = (const float*)d_in[17];
    const float* Wh1  = (const float*)d_in[18];
    const float* bh1  = (const float*)d_in[19];
    const float* Wh2  = (const float*)d_in[20];
    const float* bh2  = (const float*)d_in[21];
    float* out = (float*)d_out;

    // device-global scratch addresses (symbol lookups; no allocation)
    void *p_hid, *p_h, *p_k, *p_v, *p_tok;
    cudaGetSymbolAddress(&p_hid, g_hid);
    cudaGetSymbolAddress(&p_h,   g_h);
    cudaGetSymbolAddress(&p_k,   g_k);
    cudaGetSymbolAddress(&p_v,   g_v);
    cudaGetSymbolAddress(&p_tok, g_tok);
    float* hid = (float*)p_hid;
    float* hbf = (float*)p_h;
    float* kbf = (float*)p_k;
    float* vbf = (float*)p_v;
    int*   tok = (int*)p_tok;

    // 1) token gather + mask
    gather_tok_kernel<<<TOTAL / 256, 256>>>(mut, offs);

    // 2) hid = relu(emb[tok] @ W1 + b1)   [65536 x 2048]
    sgemm_kernel<true, true><<<dim3(HH / 128, TOTAL / 128), 256>>>(
        emb, W1, b1, hid, TOTAL, HH, DD, tok);

    // 3) h = hid @ W2 + b2                [65536 x 512]
    sgemm_kernel<false, false><<<dim3(DD / 128, TOTAL / 128), 256>>>(
        hid, W2, b2, hbf, TOTAL, DD, HH, nullptr);

    // 4) k = h @ Wk + bk ; v = h @ Wv + bv
    sgemm_kernel<false, false><<<dim3(DD / 128, TOTAL / 128), 256>>>(
        hbf, Wk, bk, kbf, TOTAL, DD, DD, nullptr);
    sgemm_kernel<false, false><<<dim3(DD / 128, TOTAL / 128), 256>>>(
        hbf, Wv, bv, vbf, TOTAL, DD, DD, nullptr);

    // 5) qp = q @ Wq + bq
    qp_kernel<<<1, DD>>>(q, Wq, bq);

    // 6) scores + softmax + ctx pooling
    attn_pool_kernel<<<BB * NHEAD, 256>>>();

    // 7) pooled = ctx @ Wo + bo
    pooled_kernel<<<BB, DD>>>(Wo, bo);

    // 8) LayerNorm + head MLP -> logits
    head_kernel<<<BB, 256>>>(ln_g, ln_b, Wh1, bh1, Wh2, bh2, out);
}

// round 2
// speedup vs baseline: 2.8752x; 2.8752x over previous
#include <cuda_runtime.h>
#include <cstdint>

#define BB 64
#define LL 1024
#define TOTAL (BB * LL)
#define DD 512
#define HH 2048
#define NHEAD 8
#define HD 64

// ---------------- scratch (static device globals; no allocation) ----------------
__device__ float g_hid[(size_t)TOTAL * HH];   // 512 MiB
__device__ float g_h  [(size_t)TOTAL * DD];   // 128 MiB
__device__ float g_k  [(size_t)TOTAL * DD];
__device__ float g_v  [(size_t)TOTAL * DD];
__device__ float g_qp [DD];
__device__ float g_ctx[BB * DD];
__device__ float g_pooled[BB * DD];
__device__ int   g_tok[TOTAL];
__device__ unsigned char g_valid[TOTAL];

// ---------------- token gather / mask ----------------
__global__ void gather_tok_kernel(const int* __restrict__ mut,
                                  const int* __restrict__ offs)
{
    int t = blockIdx.x * blockDim.x + threadIdx.x;
    if (t >= TOTAL) return;
    int b = t >> 10;
    int l = t & (LL - 1);
    int s = offs[b];
    int e = offs[b + 1];
    bool ok = l < (e - s);
    g_tok[t]   = ok ? mut[s + l] : 0;
    g_valid[t] = ok ? 1 : 0;
}

// ---------------- TF32 tensor-core GEMM ----------------
// C[M,N] = op(gather(A)[M,K] @ B[K,N] + bias), M=65536.
// Block tile 128x128, BK=32. 8 warps, warp tile 64x32. cp.async double buffer.
// Smem: As[2][128][36] (row-major, pad 4), Bs[2][32][136] (row-major, pad 8).

__device__ __forceinline__ unsigned f2tf(float x) {
    unsigned r;
    asm("cvt.rna.tf32.f32 %0, %1;" : "=r"(r) : "f"(x));
    return r;
}

__device__ __forceinline__ void mma_tf32(float* c, const unsigned* a, const unsigned* b) {
    asm volatile(
        "mma.sync.aligned.m16n8k8.row.col.f32.tf32.tf32.f32 "
        "{%0,%1,%2,%3}, {%4,%5,%6,%7}, {%8,%9}, {%0,%1,%2,%3};\n"
        : "+f"(c[0]), "+f"(c[1]), "+f"(c[2]), "+f"(c[3])
        : "r"(a[0]), "r"(a[1]), "r"(a[2]), "r"(a[3]), "r"(b[0]), "r"(b[1]));
}

__device__ __forceinline__ void cp16(float* smem_dst, const float* gsrc) {
    unsigned sdst = (unsigned)__cvta_generic_to_shared(smem_dst);
    asm volatile("cp.async.cg.shared.global [%0], [%1], 16;\n"
                 :: "r"(sdst), "l"(gsrc) : "memory");
}

#define AS_STRIDE 36
#define BS_STRIDE 136
#define AS_TILE   (128 * AS_STRIDE)   // 4608 floats per buffer
#define BS_TILE   (32 * BS_STRIDE)    // 4352 floats per buffer
#define SMEM_FLOATS (2 * AS_TILE + 2 * BS_TILE)  // 17920 floats = 71680 B

template<bool GATHER, bool RELU>
__global__ void __launch_bounds__(256, 2)
mma_gemm_kernel(const float* __restrict__ A, const float* __restrict__ Bm,
                const float* __restrict__ bias, float* __restrict__ C,
                int N, int K, const int* __restrict__ tok)
{
    extern __shared__ float sm[];
    float* As = sm;                  // [2][128][36]
    float* Bs = sm + 2 * AS_TILE;    // [2][32][136]

    const int tid  = threadIdx.x;
    const int bm   = blockIdx.y * 128;
    const int bn   = blockIdx.x * 128;
    const int warp = tid >> 5;
    const int lane = tid & 31;
    const int lm   = lane >> 2;      // 0..7
    const int lk   = lane & 3;       // 0..3
    const int wm   = (warp >> 2) * 64;
    const int wn   = (warp & 3) * 32;

    // global -> smem copy mapping
    const int arow_l = tid >> 3;        // 0..31 (+32*i)
    const int akc    = (tid & 7) << 2;  // 0,4,...,28
    const int brow_l = tid >> 5;        // 0..7 (+8*i)
    const int bnc    = lane << 2;       // 0..124

    const float* aptr[4];
#pragma unroll
    for (int i = 0; i < 4; i++) {
        int r  = bm + arow_l + i * 32;
        int ar = GATHER ? __ldg(&tok[r]) : r;
        aptr[i] = A + (size_t)ar * K + akc;
    }
    const float* bptr[4];
#pragma unroll
    for (int i = 0; i < 4; i++)
        bptr[i] = Bm + (size_t)(brow_l + i * 8) * N + bn + bnc;

    float acc[4][4][4];
#pragma unroll
    for (int mt = 0; mt < 4; mt++)
#pragma unroll
        for (int nt = 0; nt < 4; nt++)
#pragma unroll
            for (int r = 0; r < 4; r++) acc[mt][nt][r] = 0.f;

    // prologue: tile 0 into buffer 0
#pragma unroll
    for (int i = 0; i < 4; i++)
        cp16(As + (arow_l + i * 32) * AS_STRIDE + akc, aptr[i]);
#pragma unroll
    for (int i = 0; i < 4; i++)
        cp16(Bs + (brow_l + i * 8) * BS_STRIDE + bnc, bptr[i]);
    asm volatile("cp.async.commit_group;\n" ::: "memory");
    asm volatile("cp.async.wait_group 0;\n" ::: "memory");
    __syncthreads();

    const int ktiles = K >> 5;
    int buf = 0;
    for (int t = 0; t < ktiles; t++) {
        if (t + 1 < ktiles) {
            const int kt = (t + 1) << 5;
            float* Ad = As + (buf ^ 1) * AS_TILE;
            float* Bd = Bs + (buf ^ 1) * BS_TILE;
#pragma unroll
            for (int i = 0; i < 4; i++)
                cp16(Ad + (arow_l + i * 32) * AS_STRIDE + akc, aptr[i] + kt);
#pragma unroll
            for (int i = 0; i < 4; i++)
                cp16(Bd + (brow_l + i * 8) * BS_STRIDE + bnc, bptr[i] + (size_t)kt * N);
            asm volatile("cp.async.commit_group;\n" ::: "memory");
        }

        const float* Ab = As + buf * AS_TILE;
        const float* Bb = Bs + buf * BS_TILE;
#pragma unroll
        for (int ks = 0; ks < 4; ks++) {
            const int k0 = ks << 3;
            unsigned bf[4][2];
#pragma unroll
            for (int nt = 0; nt < 4; nt++) {
                const int col = wn + nt * 8 + lm;
                bf[nt][0] = f2tf(Bb[(k0 + lk) * BS_STRIDE + col]);
                bf[nt][1] = f2tf(Bb[(k0 + 4 + lk) * BS_STRIDE + col]);
            }
            unsigned af[4][4];
#pragma unroll
            for (int mt = 0; mt < 4; mt++) {
                const int row = wm + mt * 16 + lm;
                af[mt][0] = f2tf(Ab[row * AS_STRIDE + k0 + lk]);
                af[mt][1] = f2tf(Ab[(row + 8) * AS_STRIDE + k0 + lk]);
                af[mt][2] = f2tf(Ab[row * AS_STRIDE + k0 + 4 + lk]);
                af[mt][3] = f2tf(Ab[(row + 8) * AS_STRIDE + k0 + 4 + lk]);
            }
#pragma unroll
            for (int mt = 0; mt < 4; mt++)
#pragma unroll
                for (int nt = 0; nt < 4; nt++)
                    mma_tf32(acc[mt][nt], af[mt], bf[nt]);
        }

        if (t + 1 < ktiles)
            asm volatile("cp.async.wait_group 0;\n" ::: "memory");
        __syncthreads();
        buf ^= 1;
    }

    // epilogue: bias (+ReLU), float2 stores
#pragma unroll
    for (int mt = 0; mt < 4; mt++) {
        const int row = bm + wm + mt * 16 + lm;
#pragma unroll
        for (int nt = 0; nt < 4; nt++) {
            const int col = bn + wn + nt * 8 + lk * 2;
            const float2 bia = *reinterpret_cast<const float2*>(&bias[col]);
            float2 r0, r1;
            r0.x = acc[mt][nt][0] + bia.x;
            r0.y = acc[mt][nt][1] + bia.y;
            r1.x = acc[mt][nt][2] + bia.x;
            r1.y = acc[mt][nt][3] + bia.y;
            if (RELU) {
                r0.x = fmaxf(r0.x, 0.f); r0.y = fmaxf(r0.y, 0.f);
                r1.x = fmaxf(r1.x, 0.f); r1.y = fmaxf(r1.y, 0.f);
            }
            *reinterpret_cast<float2*>(&C[(size_t)row * N + col])       = r0;
            *reinterpret_cast<float2*>(&C[(size_t)(row + 8) * N + col]) = r1;
        }
    }
}

// ---------------- block reductions ----------------
__device__ __forceinline__ float block_sum(float v, float* red) {
#pragma unroll
    for (int o = 16; o > 0; o >>= 1) v += __shfl_xor_sync(0xffffffffu, v, o);
    const int wid = threadIdx.x >> 5, lid = threadIdx.x & 31;
    const int nw = blockDim.x >> 5;
    if (lid == 0) red[wid] = v;
    __syncthreads();
    if (wid == 0) {
        v = (lid < nw) ? red[lid] : 0.f;
#pragma unroll
        for (int o = 16; o > 0; o >>= 1) v += __shfl_xor_sync(0xffffffffu, v, o);
        if (lid == 0) red[0] = v;
    }
    __syncthreads();
    float r = red[0];
    __syncthreads();
    return r;
}

__device__ __forceinline__ float block_max(float v, float* red) {
#pragma unroll
    for (int o = 16; o > 0; o >>= 1) v = fmaxf(v, __shfl_xor_sync(0xffffffffu, v, o));
    const int wid = threadIdx.x >> 5, lid = threadIdx.x & 31;
    const int nw = blockDim.x >> 5;
    if (lid == 0) red[wid] = v;
    __syncthreads();
    if (wid == 0) {
        v = (lid < nw) ? red[lid] : -3.4e38f;
#pragma unroll
        for (int o = 16; o > 0; o >>= 1) v = fmaxf(v, __shfl_xor_sync(0xffffffffu, v, o));
        if (lid == 0) red[0] = v;
    }
    __syncthreads();
    float r = red[0];
    __syncthreads();
    return r;
}

// ---------------- qp = q @ Wq + bq ----------------
__global__ void qp_kernel(const float* __restrict__ q, const float* __restrict__ Wq,
                          const float* __restrict__ bq)
{
    __shared__ float qs[DD];
    const int j = threadIdx.x;
    qs[j] = q[j];
    __syncthreads();
    float s = bq[j];
    for (int i = 0; i < DD; i++) s += qs[i] * Wq[i * DD + j];
    g_qp[j] = s;
}

// ---------------- scores + softmax + ctx, one block per (b, h) ----------------
__global__ void attn_pool_kernel()
{
    const int bh = blockIdx.x;
    const int b = bh >> 3;
    const int h = bh & 7;
    const int tid = threadIdx.x; // 256

    __shared__ float qph[HD];
    __shared__ float sc[LL];
    __shared__ float red[32];
    __shared__ float part[4][HD];

    if (tid < HD) qph[tid] = g_qp[h * HD + tid];
    __syncthreads();

    const float scale = 0.125f;
    for (int l = tid; l < LL; l += 256) {
        const float* kp = g_k + ((size_t)(b * LL + l) * DD + h * HD);
        float s = 0.f;
#pragma unroll
        for (int d = 0; d < HD; d += 4) {
            float4 kv = *reinterpret_cast<const float4*>(kp + d);
            s += qph[d] * kv.x + qph[d + 1] * kv.y + qph[d + 2] * kv.z + qph[d + 3] * kv.w;
        }
        s *= scale;
        if (!g_valid[b * LL + l]) s = -1e30f;
        sc[l] = s;
    }
    __syncthreads();

    float mx = -3.4e38f;
    for (int l = tid; l < LL; l += 256) mx = fmaxf(mx, sc[l]);
    mx = block_max(mx, red);

    float sum = 0.f;
    for (int l = tid; l < LL; l += 256) {
        float e = __expf(sc[l] - mx);
        sc[l] = e;
        sum += e;
    }
    sum = block_sum(sum, red);
    const float inv = 1.f / sum;
    __syncthreads();

    const int d = tid & 63;
    const int stripe = tid >> 6;
    float acc = 0.f;
    for (int l = stripe; l < LL; l += 4)
        acc += sc[l] * g_v[(size_t)(b * LL + l) * DD + h * HD + d];
    part[stripe][d] = acc;
    __syncthreads();
    if (tid < HD) {
        float c = (part[0][tid] + part[1][tid] + part[2][tid] + part[3][tid]) * inv;
        g_ctx[b * DD + h * HD + tid] = c;
    }
}

// ---------------- pooled = ctx @ Wo + bo ----------------
__global__ void pooled_kernel(const float* __restrict__ Wo, const float* __restrict__ bo)
{
    const int b = blockIdx.x;
    const int j = threadIdx.x;
    __shared__ float cx[DD];
    cx[j] = g_ctx[b * DD + j];
    __syncthreads();
    float s = bo[j];
    for (int i = 0; i < DD; i++) s += cx[i] * Wo[i * DD + j];
    g_pooled[b * DD + j] = s;
}

// ---------------- LayerNorm + head MLP -> logit ----------------
__global__ void head_kernel(const float* __restrict__ ln_g, const float* __restrict__ ln_b,
                            const float* __restrict__ Wh1, const float* __restrict__ bh1,
                            const float* __restrict__ Wh2, const float* __restrict__ bh2,
                            float* __restrict__ out)
{
    const int b = blockIdx.x;
    const int tid = threadIdx.x; // 256
    __shared__ float y[DD];
    __shared__ float red[32];

    float s = 0.f;
    for (int i = tid; i < DD; i += 256) s += g_pooled[b * DD + i];
    const float mu = block_sum(s, red) * (1.f / DD);

    float vs = 0.f;
    for (int i = tid; i < DD; i += 256) {
        float dd = g_pooled[b * DD + i] - mu;
        vs += dd * dd;
    }
    const float var = block_sum(vs, red) * (1.f / DD);
    const float rstd = rsqrtf(var + 1e-5f);

    for (int i = tid; i < DD; i += 256)
        y[i] = (g_pooled[b * DD + i] - mu) * rstd * ln_g[i] + ln_b[i];
    __syncthreads();

    float acc = 0.f;
    for (int j = tid; j < HH; j += 256) {
        float t = bh1[j];
        for (int i = 0; i < DD; i++) t += y[i] * Wh1[i * HH + j];
        acc += fmaxf(t, 0.f) * Wh2[j];
    }
    const float tot = block_sum(acc, red);
    if (tid == 0) out[b] = tot + bh2[0];
}

// ---------------- launcher ----------------
extern "C" void kernel_launch(void* const* d_in, const int* in_sizes, int n_in,
                              void* d_out, int out_size)
{
    const int*   mut  = (const int*)d_in[0];
    const int*   offs = (const int*)d_in[1];
    const float* emb  = (const float*)d_in[2];
    const float* W1   = (const float*)d_in[3];
    const float* b1   = (const float*)d_in[4];
    const float* W2   = (const float*)d_in[5];
    const float* b2   = (const float*)d_in[6];
    const float* q    = (const float*)d_in[7];
    const float* Wq   = (const float*)d_in[8];
    const float* bq   = (const float*)d_in[9];
    const float* Wk   = (const float*)d_in[10];
    const float* bk   = (const float*)d_in[11];
    const float* Wv   = (const float*)d_in[12];
    const float* bv   = (const float*)d_in[13];
    const float* Wo   = (const float*)d_in[14];
    const float* bo   = (const float*)d_in[15];
    const float* ln_g = (const float*)d_in[16];
    const float* ln_b = (const float*)d_in[17];
    const float* Wh1  = (const float*)d_in[18];
    const float* bh1  = (const float*)d_in[19];
    const float* Wh2  = (const float*)d_in[20];
    const float* bh2  = (const float*)d_in[21];
    float* out = (float*)d_out;

    void *p_hid, *p_h, *p_k, *p_v, *p_tok;
    cudaGetSymbolAddress(&p_hid, g_hid);
    cudaGetSymbolAddress(&p_h,   g_h);
    cudaGetSymbolAddress(&p_k,   g_k);
    cudaGetSymbolAddress(&p_v,   g_v);
    cudaGetSymbolAddress(&p_tok, g_tok);
    float* hid = (float*)p_hid;
    float* hbf = (float*)p_h;
    float* kbf = (float*)p_k;
    float* vbf = (float*)p_v;
    int*   tok = (int*)p_tok;

    const int smem_bytes = SMEM_FLOATS * 4;  // 71680
    cudaFuncSetAttribute(mma_gemm_kernel<true, true>,
                         cudaFuncAttributeMaxDynamicSharedMemorySize, smem_bytes);
    cudaFuncSetAttribute(mma_gemm_kernel<false, false>,
                         cudaFuncAttributeMaxDynamicSharedMemorySize, smem_bytes);

    // 1) token gather + mask
    gather_tok_kernel<<<TOTAL / 256, 256>>>(mut, offs);

    // 2) hid = relu(emb[tok] @ W1 + b1)   [65536 x 2048], K=512
    mma_gemm_kernel<true, true><<<dim3(HH / 128, TOTAL / 128), 256, smem_bytes>>>(
        emb, W1, b1, hid, HH, DD, tok);

    // 3) h = hid @ W2 + b2                [65536 x 512], K=2048
    mma_gemm_kernel<false, false><<<dim3(DD / 128, TOTAL / 128), 256, smem_bytes>>>(
        hid, W2, b2, hbf, DD, HH, nullptr);

    // 4) k = h @ Wk + bk ; v = h @ Wv + bv   [65536 x 512], K=512
    mma_gemm_kernel<false, false><<<dim3(DD / 128, TOTAL / 128), 256, smem_bytes>>>(
        hbf, Wk, bk, kbf, DD, DD, nullptr);
    mma_gemm_kernel<false, false><<<dim3(DD / 128, TOTAL / 128), 256, smem_bytes>>>(
        hbf, Wv, bv, vbf, DD, DD, nullptr);

    // 5) qp = q @ Wq + bq
    qp_kernel<<<1, DD>>>(q, Wq, bq);

    // 6) scores + softmax + ctx pooling
    attn_pool_kernel<<<BB * NHEAD, 256>>>();

    // 7) pooled = ctx @ Wo + bo
    pooled_kernel<<<BB, DD>>>(Wo, bo);

    // 8) LayerNorm + head MLP -> logits
    head_kernel<<<BB, 256>>>(ln_g, ln_b, Wh1, bh1, Wh2, bh2, out);
}

// round 3
// speedup vs baseline: 3.2427x; 1.1278x over previous
#include <cuda_runtime.h>
#include <cstdint>

#define BB 64
#define LL 1024
#define TOTAL (BB * LL)
#define DD 512
#define HH 2048
#define NHEAD 8
#define HD 64

// ---------------- scratch (static device globals; no allocation) ----------------
__device__ float g_hid[(size_t)TOTAL * HH];   // 512 MiB (tf32-rounded values)
__device__ float g_h  [(size_t)TOTAL * DD];   // 128 MiB
__device__ float g_w1t[(size_t)DD * HH];      // tf32 W1
__device__ float g_w2t[(size_t)HH * DD];      // tf32 W2
__device__ float g_s  [BB * NHEAD * LL];      // scores -> softmax in place
__device__ float g_hbar[BB * NHEAD * DD];
__device__ float g_qp [DD];
__device__ float g_wk_eff[DD * NHEAD];        // Wk @ qp (per head)
__device__ float g_bk_eff[NHEAD];
__device__ float g_ctx[BB * DD];
__device__ float g_pooled[BB * DD];
__device__ int   g_tok[TOTAL];
__device__ unsigned char g_valid[TOTAL];

// ---------------- token gather / mask ----------------
__global__ void gather_tok_kernel(const int* __restrict__ mut,
                                  const int* __restrict__ offs)
{
    int t = blockIdx.x * blockDim.x + threadIdx.x;
    if (t >= TOTAL) return;
    int b = t >> 10;
    int l = t & (LL - 1);
    int s = offs[b];
    int e = offs[b + 1];
    bool ok = l < (e - s);
    g_tok[t]   = ok ? mut[s + l] : 0;
    g_valid[t] = ok ? 1 : 0;
}

// ---------------- tf32 helpers ----------------
__device__ __forceinline__ unsigned f2tf(float x) {
    unsigned r;
    asm("cvt.rna.tf32.f32 %0, %1;" : "=r"(r) : "f"(x));
    return r;
}

template<bool CVT>
__device__ __forceinline__ unsigned ldfrag(const float* p) {
    float v = *p;
    return CVT ? f2tf(v) : __float_as_uint(v);
}

__device__ __forceinline__ void mma_tf32(float* c, const unsigned* a, const unsigned* b) {
    asm volatile(
        "mma.sync.aligned.m16n8k8.row.col.f32.tf32.tf32.f32 "
        "{%0,%1,%2,%3}, {%4,%5,%6,%7}, {%8,%9}, {%0,%1,%2,%3};\n"
        : "+f"(c[0]), "+f"(c[1]), "+f"(c[2]), "+f"(c[3])
        : "r"(a[0]), "r"(a[1]), "r"(a[2]), "r"(a[3]), "r"(b[0]), "r"(b[1]));
}

__device__ __forceinline__ void cp16(float* smem_dst, const float* gsrc) {
    unsigned sdst = (unsigned)__cvta_generic_to_shared(smem_dst);
    asm volatile("cp.async.cg.shared.global [%0], [%1], 16;\n"
                 :: "r"(sdst), "l"(gsrc) : "memory");
}

// weight pre-conversion: fp32 -> tf32-rounded fp32 bit pattern
__global__ void cvt_tf32_kernel(const float* __restrict__ src, float* __restrict__ dst, int n)
{
    int i = blockIdx.x * blockDim.x + threadIdx.x;
    if (i < n) dst[i] = __uint_as_float(f2tf(src[i]));
}

// ---------------- TF32 tensor-core GEMM ----------------
#define AS_STRIDE 36
#define BS_STRIDE 136
#define AS_TILE   (128 * AS_STRIDE)
#define BS_TILE   (32 * BS_STRIDE)
#define SMEM_FLOATS (2 * AS_TILE + 2 * BS_TILE)  // 71680 B

template<bool GATHER, bool RELU, bool CVTA, bool TFOUT>
__global__ void __launch_bounds__(256, 2)
mma_gemm_kernel(const float* __restrict__ A, const float* __restrict__ Bm,
                const float* __restrict__ bias, float* __restrict__ C,
                int N, int K, const int* __restrict__ tok)
{
    extern __shared__ float sm[];
    float* As = sm;
    float* Bs = sm + 2 * AS_TILE;

    const int tid  = threadIdx.x;
    const int bm   = blockIdx.y * 128;
    const int bn   = blockIdx.x * 128;
    const int warp = tid >> 5;
    const int lane = tid & 31;
    const int lm   = lane >> 2;
    const int lk   = lane & 3;
    const int wm   = (warp >> 2) * 64;
    const int wn   = (warp & 3) * 32;

    const int arow_l = tid >> 3;
    const int akc    = (tid & 7) << 2;
    const int brow_l = tid >> 5;
    const int bnc    = lane << 2;

    const float* aptr[4];
#pragma unroll
    for (int i = 0; i < 4; i++) {
        int r  = bm + arow_l + i * 32;
        int ar = GATHER ? __ldg(&tok[r]) : r;
        aptr[i] = A + (size_t)ar * K + akc;
    }
    const float* bptr[4];
#pragma unroll
    for (int i = 0; i < 4; i++)
        bptr[i] = Bm + (size_t)(brow_l + i * 8) * N + bn + bnc;

    float acc[4][4][4];
#pragma unroll
    for (int mt = 0; mt < 4; mt++)
#pragma unroll
        for (int nt = 0; nt < 4; nt++)
#pragma unroll
            for (int r = 0; r < 4; r++) acc[mt][nt][r] = 0.f;

#pragma unroll
    for (int i = 0; i < 4; i++)
        cp16(As + (arow_l + i * 32) * AS_STRIDE + akc, aptr[i]);
#pragma unroll
    for (int i = 0; i < 4; i++)
        cp16(Bs + (brow_l + i * 8) * BS_STRIDE + bnc, bptr[i]);
    asm volatile("cp.async.commit_group;\n" ::: "memory");
    asm volatile("cp.async.wait_group 0;\n" ::: "memory");
    __syncthreads();

    const int ktiles = K >> 5;
    int buf = 0;
    for (int t = 0; t < ktiles; t++) {
        if (t + 1 < ktiles) {
            const int kt = (t + 1) << 5;
            float* Ad = As + (buf ^ 1) * AS_TILE;
            float* Bd = Bs + (buf ^ 1) * BS_TILE;
#pragma unroll
            for (int i = 0; i < 4; i++)
                cp16(Ad + (arow_l + i * 32) * AS_STRIDE + akc, aptr[i] + kt);
#pragma unroll
            for (int i = 0; i < 4; i++)
                cp16(Bd + (brow_l + i * 8) * BS_STRIDE + bnc, bptr[i] + (size_t)kt * N);
            asm volatile("cp.async.commit_group;\n" ::: "memory");
        }

        const float* Ab = As + buf * AS_TILE;
        const float* Bb = Bs + buf * BS_TILE;
#pragma unroll
        for (int ks = 0; ks < 4; ks++) {
            const int k0 = ks << 3;
            unsigned bf[4][2];
#pragma unroll
            for (int nt = 0; nt < 4; nt++) {
                const int col = wn + nt * 8 + lm;
                bf[nt][0] = ldfrag<false>(&Bb[(k0 + lk) * BS_STRIDE + col]);
                bf[nt][1] = ldfrag<false>(&Bb[(k0 + 4 + lk) * BS_STRIDE + col]);
            }
            unsigned af[4][4];
#pragma unroll
            for (int mt = 0; mt < 4; mt++) {
                const int row = wm + mt * 16 + lm;
                af[mt][0] = ldfrag<CVTA>(&Ab[row * AS_STRIDE + k0 + lk]);
                af[mt][1] = ldfrag<CVTA>(&Ab[(row + 8) * AS_STRIDE + k0 + lk]);
                af[mt][2] = ldfrag<CVTA>(&Ab[row * AS_STRIDE + k0 + 4 + lk]);
                af[mt][3] = ldfrag<CVTA>(&Ab[(row + 8) * AS_STRIDE + k0 + 4 + lk]);
            }
#pragma unroll
            for (int mt = 0; mt < 4; mt++)
#pragma unroll
                for (int nt = 0; nt < 4; nt++)
                    mma_tf32(acc[mt][nt], af[mt], bf[nt]);
        }

        if (t + 1 < ktiles)
            asm volatile("cp.async.wait_group 0;\n" ::: "memory");
        __syncthreads();
        buf ^= 1;
    }

#pragma unroll
    for (int mt = 0; mt < 4; mt++) {
        const int row = bm + wm + mt * 16 + lm;
#pragma unroll
        for (int nt = 0; nt < 4; nt++) {
            const int col = bn + wn + nt * 8 + lk * 2;
            const float2 bia = *reinterpret_cast<const float2*>(&bias[col]);
            float2 r0, r1;
            r0.x = acc[mt][nt][0] + bia.x;
            r0.y = acc[mt][nt][1] + bia.y;
            r1.x = acc[mt][nt][2] + bia.x;
            r1.y = acc[mt][nt][3] + bia.y;
            if (RELU) {
                r0.x = fmaxf(r0.x, 0.f); r0.y = fmaxf(r0.y, 0.f);
                r1.x = fmaxf(r1.x, 0.f); r1.y = fmaxf(r1.y, 0.f);
            }
            if (TFOUT) {
                r0.x = __uint_as_float(f2tf(r0.x)); r0.y = __uint_as_float(f2tf(r0.y));
                r1.x = __uint_as_float(f2tf(r1.x)); r1.y = __uint_as_float(f2tf(r1.y));
            }
            *reinterpret_cast<float2*>(&C[(size_t)row * N + col])       = r0;
            *reinterpret_cast<float2*>(&C[(size_t)(row + 8) * N + col]) = r1;
        }
    }
}

// ---------------- block reductions ----------------
__device__ __forceinline__ float block_sum(float v, float* red) {
#pragma unroll
    for (int o = 16; o > 0; o >>= 1) v += __shfl_xor_sync(0xffffffffu, v, o);
    const int wid = threadIdx.x >> 5, lid = threadIdx.x & 31;
    const int nw = blockDim.x >> 5;
    if (lid == 0) red[wid] = v;
    __syncthreads();
    if (wid == 0) {
        v = (lid < nw) ? red[lid] : 0.f;
#pragma unroll
        for (int o = 16; o > 0; o >>= 1) v += __shfl_xor_sync(0xffffffffu, v, o);
        if (lid == 0) red[0] = v;
    }
    __syncthreads();
    float r = red[0];
    __syncthreads();
    return r;
}

__device__ __forceinline__ float block_max(float v, float* red) {
#pragma unroll
    for (int o = 16; o > 0; o >>= 1) v = fmaxf(v, __shfl_xor_sync(0xffffffffu, v, o));
    const int wid = threadIdx.x >> 5, lid = threadIdx.x & 31;
    const int nw = blockDim.x >> 5;
    if (lid == 0) red[wid] = v;
    __syncthreads();
    if (wid == 0) {
        v = (lid < nw) ? red[lid] : -3.4e38f;
#pragma unroll
        for (int o = 16; o > 0; o >>= 1) v = fmaxf(v, __shfl_xor_sync(0xffffffffu, v, o));
        if (lid == 0) red[0] = v;
    }
    __syncthreads();
    float r = red[0];
    __syncthreads();
    return r;
}

// ---------------- qp = q @ Wq + bq ----------------
__global__ void qp_kernel(const float* __restrict__ q, const float* __restrict__ Wq,
                          const float* __restrict__ bq)
{
    __shared__ float qs[DD];
    const int j = threadIdx.x;
    qs[j] = q[j];
    __syncthreads();
    float s = bq[j];
    for (int i = 0; i < DD; i++) s += qs[i] * Wq[i * DD + j];
    g_qp[j] = s;
}

// ---------------- wk_eff[i,h] = sum_d Wk[i, h*64+d] * qp[h*64+d]; bk_eff ----------------
__global__ void wk_eff_kernel(const float* __restrict__ Wk, const float* __restrict__ bk)
{
    __shared__ float qs[DD];
    const int i = threadIdx.x;   // 512
    qs[i] = g_qp[i];
    __syncthreads();
    const float* wr = Wk + (size_t)i * DD;
#pragma unroll
    for (int h = 0; h < NHEAD; h++) {
        float s = 0.f;
#pragma unroll
        for (int d = 0; d < HD; d++) s += wr[h * HD + d] * qs[h * HD + d];
        g_wk_eff[i * NHEAD + h] = s;
    }
    if (i < NHEAD) {
        float s = 0.f;
        for (int d = 0; d < HD; d++) s += bk[i * HD + d] * qs[i * HD + d];
        g_bk_eff[i] = s;
    }
}

// ---------------- scores: s[b,h,l] = (h_l . wk_eff[:,h] + bk_eff[h]) / 8, masked ----------------
// one block = 128 rows; warp per row, lane-split over 512 cols
__global__ void scores_kernel()
{
    __shared__ float wk_s[DD][NHEAD];   // 16 KB
    __shared__ float bk_s[NHEAD];
    const int tid  = threadIdx.x;       // 256
    const int warp = tid >> 5;
    const int lane = tid & 31;

    for (int i = tid; i < DD * NHEAD; i += 256)
        (&wk_s[0][0])[i] = g_wk_eff[i];
    if (tid < NHEAD) bk_s[tid] = g_bk_eff[tid];
    __syncthreads();

    const int row0 = blockIdx.x * 128;
    for (int it = 0; it < 16; it++) {
        const int row = row0 + it * 8 + warp;
        const float* hp = g_h + (size_t)row * DD;
        float acc[NHEAD];
#pragma unroll
        for (int h = 0; h < NHEAD; h++) acc[h] = 0.f;
#pragma unroll
        for (int c = 0; c < 16; c++) {
            const int i = lane + c * 32;
            const float hv = hp[i];
#pragma unroll
            for (int h = 0; h < NHEAD; h++) acc[h] += hv * wk_s[i][h];
        }
#pragma unroll
        for (int h = 0; h < NHEAD; h++) {
#pragma unroll
            for (int o = 16; o > 0; o >>= 1)
                acc[h] += __shfl_xor_sync(0xffffffffu, acc[h], o);
        }
        if (lane < NHEAD) {
            const int b = row >> 10;
            const int l = row & (LL - 1);
            float s = (acc[lane] + bk_s[lane]) * 0.125f;
            if (!g_valid[row]) s = -1e30f;
            g_s[(b * NHEAD + lane) * LL + l] = s;
        }
    }
}

// ---------------- softmax over l per (b,h), in place ----------------
__global__ void softmax_kernel()
{
    const int bh = blockIdx.x;
    const int tid = threadIdx.x;  // 256
    __shared__ float red[32];
    float* sp = g_s + (size_t)bh * LL;

    float v0 = sp[tid], v1 = sp[tid + 256], v2 = sp[tid + 512], v3 = sp[tid + 768];
    float mx = fmaxf(fmaxf(v0, v1), fmaxf(v2, v3));
    mx = block_max(mx, red);
    float e0 = __expf(v0 - mx), e1 = __expf(v1 - mx);
    float e2 = __expf(v2 - mx), e3 = __expf(v3 - mx);
    float sum = block_sum(e0 + e1 + e2 + e3, red);
    const float inv = 1.f / sum;
    sp[tid] = e0 * inv; sp[tid + 256] = e1 * inv;
    sp[tid + 512] = e2 * inv; sp[tid + 768] = e3 * inv;
}

// ---------------- hbar[b,h,:] = sum_l a[b,h,l] * h[b,l,:] ----------------
__global__ void __launch_bounds__(512)
hbar_kernel()
{
    const int b = blockIdx.x;     // 64 blocks
    const int d = threadIdx.x;    // 512
    __shared__ float a_s[NHEAD][LL];  // 32 KB

    for (int i = d; i < NHEAD * LL; i += 512)
        (&a_s[0][0])[i] = g_s[(size_t)b * NHEAD * LL + i];
    __syncthreads();

    float acc[NHEAD];
#pragma unroll
    for (int h = 0; h < NHEAD; h++) acc[h] = 0.f;

    const float* hp = g_h + (size_t)b * LL * DD + d;
#pragma unroll 4
    for (int l = 0; l < LL; l++) {
        const float hv = hp[(size_t)l * DD];
#pragma unroll
        for (int h = 0; h < NHEAD; h++) acc[h] += a_s[h][l] * hv;
    }
#pragma unroll
    for (int h = 0; h < NHEAD; h++)
        g_hbar[(b * NHEAD + h) * DD + d] = acc[h];
}

// ---------------- ctx[b, h*64+d] = hbar[b,h,:] @ Wv[:, h*64+d] + bv ----------------
__global__ void ctx_kernel(const float* __restrict__ Wv, const float* __restrict__ bv)
{
    const int b = blockIdx.x;
    const int j = threadIdx.x;   // 512
    __shared__ float hb[NHEAD][DD];  // 16 KB
    for (int i = j; i < NHEAD * DD; i += 512)
        (&hb[0][0])[i] = g_hbar[b * NHEAD * DD + i];
    __syncthreads();
    const int h = j >> 6;
    float s = bv[j];
    for (int i = 0; i < DD; i++) s += hb[h][i] * Wv[(size_t)i * DD + j];
    g_ctx[b * DD + j] = s;
}

// ---------------- pooled = ctx @ Wo + bo ----------------
__global__ void pooled_kernel(const float* __restrict__ Wo, const float* __restrict__ bo)
{
    const int b = blockIdx.x;
    const int j = threadIdx.x;
    __shared__ float cx[DD];
    cx[j] = g_ctx[b * DD + j];
    __syncthreads();
    float s = bo[j];
    for (int i = 0; i < DD; i++) s += cx[i] * Wo[(size_t)i * DD + j];
    g_pooled[b * DD + j] = s;
}

// ---------------- LayerNorm + head MLP -> logit ----------------
__global__ void head_kernel(const float* __restrict__ ln_g, const float* __restrict__ ln_b,
                            const float* __restrict__ Wh1, const float* __restrict__ bh1,
                            const float* __restrict__ Wh2, const float* __restrict__ bh2,
                            float* __restrict__ out)
{
    const int b = blockIdx.x;
    const int tid = threadIdx.x; // 256
    __shared__ float y[DD];
    __shared__ float red[32];

    float s = 0.f;
    for (int i = tid; i < DD; i += 256) s += g_pooled[b * DD + i];
    const float mu = block_sum(s, red) * (1.f / DD);

    float vs = 0.f;
    for (int i = tid; i < DD; i += 256) {
        float dd = g_pooled[b * DD + i] - mu;
        vs += dd * dd;
    }
    const float var = block_sum(vs, red) * (1.f / DD);
    const float rstd = rsqrtf(var + 1e-5f);

    for (int i = tid; i < DD; i += 256)
        y[i] = (g_pooled[b * DD + i] - mu) * rstd * ln_g[i] + ln_b[i];
    __syncthreads();

    float acc = 0.f;
    for (int j = tid; j < HH; j += 256) {
        float t = bh1[j];
        for (int i = 0; i < DD; i++) t += y[i] * Wh1[(size_t)i * HH + j];
        acc += fmaxf(t, 0.f) * Wh2[j];
    }
    const float tot = block_sum(acc, red);
    if (tid == 0) out[b] = tot + bh2[0];
}

// ---------------- launcher ----------------
extern "C" void kernel_launch(void* const* d_in, const int* in_sizes, int n_in,
                              void* d_out, int out_size)
{
    const int*   mut  = (const int*)d_in[0];
    const int*   offs = (const int*)d_in[1];
    const float* emb  = (const float*)d_in[2];
    const float* W1   = (const float*)d_in[3];
    const float* b1   = (const float*)d_in[4];
    const float* W2   = (const float*)d_in[5];
    const float* b2   = (const float*)d_in[6];
    const float* q    = (const float*)d_in[7];
    const float* Wq   = (const float*)d_in[8];
    const float* bq   = (const float*)d_in[9];
    const float* Wk   = (const float*)d_in[10];
    const float* bk   = (const float*)d_in[11];
    const float* Wv   = (const float*)d_in[12];
    const float* bv   = (const float*)d_in[13];
    const float* Wo   = (const float*)d_in[14];
    const float* bo   = (const float*)d_in[15];
    const float* ln_g = (const float*)d_in[16];
    const float* ln_b = (const float*)d_in[17];
    const float* Wh1  = (const float*)d_in[18];
    const float* bh1  = (const float*)d_in[19];
    const float* Wh2  = (const float*)d_in[20];
    const float* bh2  = (const float*)d_in[21];
    float* out = (float*)d_out;

    void *p_hid, *p_h, *p_w1t, *p_w2t, *p_tok;
    cudaGetSymbolAddress(&p_hid, g_hid);
    cudaGetSymbolAddress(&p_h,   g_h);
    cudaGetSymbolAddress(&p_w1t, g_w1t);
    cudaGetSymbolAddress(&p_w2t, g_w2t);
    cudaGetSymbolAddress(&p_tok, g_tok);
    float* hid = (float*)p_hid;
    float* hbf = (float*)p_h;
    float* w1t = (float*)p_w1t;
    float* w2t = (float*)p_w2t;
    int*   tok = (int*)p_tok;

    const int smem_bytes = SMEM_FLOATS * 4;
    cudaFuncSetAttribute(mma_gemm_kernel<true, true, true, true>,
                         cudaFuncAttributeMaxDynamicSharedMemorySize, smem_bytes);
    cudaFuncSetAttribute(mma_gemm_kernel<false, false, false, false>,
                         cudaFuncAttributeMaxDynamicSharedMemorySize, smem_bytes);

    // 0) weight pre-conversion to tf32 bit patterns (1M elems each)
    cvt_tf32_kernel<<<(DD * HH) / 256, 256>>>(W1, w1t, DD * HH);
    cvt_tf32_kernel<<<(HH * DD) / 256, 256>>>(W2, w2t, HH * DD);

    // 1) token gather + mask
    gather_tok_kernel<<<TOTAL / 256, 256>>>(mut, offs);

    // 2) hid = tf32round(relu(emb[tok] @ W1 + b1))   [65536 x 2048], K=512
    mma_gemm_kernel<true, true, true, true><<<dim3(HH / 128, TOTAL / 128), 256, smem_bytes>>>(
        emb, w1t, b1, hid, HH, DD, tok);

    // 3) h = hid @ W2 + b2                [65536 x 512], K=2048 (zero cvt)
    mma_gemm_kernel<false, false, false, false><<<dim3(DD / 128, TOTAL / 128), 256, smem_bytes>>>(
        hid, w2t, b2, hbf, DD, HH, nullptr);

    // 4) qp, wk_eff
    qp_kernel<<<1, DD>>>(q, Wq, bq);
    wk_eff_kernel<<<1, DD>>>(Wk, bk);

    // 5) scores (k GEMM folded into wk_eff), softmax
    scores_kernel<<<TOTAL / 128, 256>>>();
    softmax_kernel<<<BB * NHEAD, 256>>>();

    // 6) hbar = a-weighted sum of h; ctx = hbar @ Wv (v GEMM folded)
    hbar_kernel<<<BB, 512>>>();
    ctx_kernel<<<BB, DD>>>(Wv, bv);

    // 7) pooled = ctx @ Wo + bo
    pooled_kernel<<<BB, DD>>>(Wo, bo);

    // 8) LayerNorm + head MLP -> logits
    head_kernel<<<BB, 256>>>(ln_g, ln_b, Wh1, bh1, Wh2, bh2, out);
}

// round 5
// speedup vs baseline: 3.9827x; 1.2282x over previous
#include <cuda_runtime.h>
#include <cstdint>

#define BB 64
#define LL 1024
#define TOTAL (BB * LL)
#define DD 512
#define HH 2048
#define NHEAD 8
#define HD 64

// ---------------- scratch (static device globals; no allocation) ----------------
__device__ float g_z  [(size_t)TOTAL * DD];   // 128 MiB gathered emb, tf32-rounded
__device__ float g_hid[(size_t)TOTAL * HH];   // 512 MiB hidden, tf32-rounded
__device__ float g_h  [(size_t)TOTAL * DD];   // 128 MiB
__device__ float g_w1t[(size_t)HH * DD];      // W1^T [N=2048][K=512] tf32-rounded
__device__ float g_w2t[(size_t)DD * HH];      // W2^T [N=512][K=2048] tf32-rounded
__device__ float g_s  [BB * NHEAD * LL];
__device__ float g_hbarp[4 * BB * NHEAD * DD];
__device__ float g_qp [DD];
__device__ float g_wk_eff[DD * NHEAD];
__device__ float g_bk_eff[NHEAD];
__device__ float g_ctx[BB * DD];
__device__ float g_y  [BB * DD];
__device__ float g_hpart[BB * 8];
__device__ int   g_tok[TOTAL];
__device__ unsigned char g_valid[TOTAL];

// ---------------- helpers ----------------
__device__ __forceinline__ unsigned f2tf(float x) {
    unsigned r;
    asm("cvt.rna.tf32.f32 %0, %1;" : "=r"(r) : "f"(x));
    return r;
}

__device__ __forceinline__ void mma_tf32(float* c, const unsigned* a, const unsigned* b) {
    asm volatile(
        "mma.sync.aligned.m16n8k8.row.col.f32.tf32.tf32.f32 "
        "{%0,%1,%2,%3}, {%4,%5,%6,%7}, {%8,%9}, {%0,%1,%2,%3};\n"
        : "+f"(c[0]), "+f"(c[1]), "+f"(c[2]), "+f"(c[3])
        : "r"(a[0]), "r"(a[1]), "r"(a[2]), "r"(a[3]), "r"(b[0]), "r"(b[1]));
}

__device__ __forceinline__ void cp16(float* smem_dst, const float* gsrc) {
    unsigned sdst = (unsigned)__cvta_generic_to_shared(smem_dst);
    asm volatile("cp.async.cg.shared.global [%0], [%1], 16;\n"
                 :: "r"(sdst), "l"(gsrc) : "memory");
}

// ---------------- token gather / mask ----------------
__global__ void gather_tok_kernel(const int* __restrict__ mut,
                                  const int* __restrict__ offs)
{
    int t = blockIdx.x * blockDim.x + threadIdx.x;
    if (t >= TOTAL) return;
    int b = t >> 10;
    int l = t & (LL - 1);
    int s = offs[b];
    int e = offs[b + 1];
    bool ok = l < (e - s);
    g_tok[t]   = ok ? mut[s + l] : 0;
    g_valid[t] = ok ? 1 : 0;
}

// ---------------- pre-pass: gathered emb -> tf32-rounded fp32 ----------------
__global__ void ztf_kernel(const float* __restrict__ emb)
{
    int gid = blockIdx.x * blockDim.x + threadIdx.x;   // TOTAL*128 threads
    int r = gid >> 7;
    int c = (gid & 127) << 2;
    int t = g_tok[r];
    float4 v = *reinterpret_cast<const float4*>(emb + (size_t)t * DD + c);
    v.x = __uint_as_float(f2tf(v.x));
    v.y = __uint_as_float(f2tf(v.y));
    v.z = __uint_as_float(f2tf(v.z));
    v.w = __uint_as_float(f2tf(v.w));
    *reinterpret_cast<float4*>(g_z + (size_t)r * DD + c) = v;
}

// ---------------- pre-pass: W [K][N] -> W^T [N][K] tf32-rounded ----------------
__global__ void wttf_kernel(const float* __restrict__ W, float* __restrict__ WT,
                            int K, int N)
{
    __shared__ float tile[32][33];
    const int k0 = blockIdx.y * 32, n0 = blockIdx.x * 32;
    const int tx = threadIdx.x, ty = threadIdx.y;  // 32 x 8
#pragma unroll
    for (int i = 0; i < 4; i++)
        tile[ty + i * 8][tx] = W[(size_t)(k0 + ty + i * 8) * N + n0 + tx];
    __syncthreads();
#pragma unroll
    for (int i = 0; i < 4; i++)
        WT[(size_t)(n0 + ty + i * 8) * K + k0 + tx] =
            __uint_as_float(f2tf(tile[tx][ty + i * 8]));
}

// ---------------- tf32 tensor-core GEMM: 256x128 block, 8 warps 64x64 ----------
#define BM 256
#define BN 128
#define BKT 32
#define A_ST (BM * BKT)    // 8192 floats / stage
#define B_ST (BN * BKT)    // 4096 floats / stage
#define NSTAGE 3
#define GSMEM ((A_ST + B_ST) * NSTAGE * 4)  // 147456 B

template<bool TFOUT, bool RELU>
__global__ void __launch_bounds__(256, 1)
tf32_gemm_kernel(const float* __restrict__ A, const float* __restrict__ Bt,
                 const float* __restrict__ bias, float* __restrict__ C,
                 int N, int K)
{
    extern __shared__ float sm[];
    float* As = sm;                   // [3][256][32]
    float* Bs = sm + NSTAGE * A_ST;   // [3][128][32]

    const int tid  = threadIdx.x;
    const int bm   = blockIdx.y * BM;
    const int bn   = blockIdx.x * BN;
    const int warp = tid >> 5;
    const int lane = tid & 31;
    const int lm   = lane >> 2;
    const int lk   = lane & 3;
    const int wm   = (warp & 3) * 64;
    const int wn   = (warp >> 2) * 64;

    // copy mapping: base row = tid>>3, chunk j = tid&7; A: +p*32 rows (p<8), B: p<4
    const int crow = tid >> 3;
    const int cj   = tid & 7;
    const int sw8  = (cj ^ (crow & 7)) << 2;
    const float* A0 = A  + (size_t)(bm + crow) * K + cj * 4;
    const float* B0 = Bt + (size_t)(bn + crow) * K + cj * 4;
    const int ad0 = crow * 32 + sw8;    // + p*1024
    const size_t k32 = (size_t)32 * K;

    float acc[4][8][4];
#pragma unroll
    for (int mt = 0; mt < 4; mt++)
#pragma unroll
        for (int nt = 0; nt < 8; nt++)
#pragma unroll
            for (int r = 0; r < 4; r++) acc[mt][nt][r] = 0.f;

    const int ktiles = K >> 5;

    // prologue: stages 0,1
#pragma unroll
    for (int s = 0; s < 2; s++) {
        float* Ad = As + s * A_ST;
        float* Bd = Bs + s * B_ST;
#pragma unroll
        for (int p = 0; p < 8; p++) cp16(Ad + ad0 + p * 1024, A0 + p * k32 + s * 32);
#pragma unroll
        for (int p = 0; p < 4; p++) cp16(Bd + ad0 + p * 1024, B0 + p * k32 + s * 32);
        asm volatile("cp.async.commit_group;\n" ::: "memory");
    }
    asm volatile("cp.async.wait_group 1;\n" ::: "memory");
    __syncthreads();

    int sload = 2, scomp = 0;
    for (int t = 0; t < ktiles; t++) {
        if (t + 2 < ktiles) {
            float* Ad = As + sload * A_ST;
            float* Bd = Bs + sload * B_ST;
            const int kt = (t + 2) * 32;
#pragma unroll
            for (int p = 0; p < 8; p++) cp16(Ad + ad0 + p * 1024, A0 + p * k32 + kt);
#pragma unroll
            for (int p = 0; p < 4; p++) cp16(Bd + ad0 + p * 1024, B0 + p * k32 + kt);
            asm volatile("cp.async.commit_group;\n" ::: "memory");
            if (++sload == NSTAGE) sload = 0;
        }

        const float* Ab = As + scomp * A_ST;
        const float* Bb = Bs + scomp * B_ST;
#pragma unroll
        for (int ks = 0; ks < 4; ks++) {
            const int c0 = 2 * ks, c1 = 2 * ks + 1;
            unsigned bfr[8][2];
#pragma unroll
            for (int nt = 0; nt < 8; nt++) {
                const int n  = wn + nt * 8 + lm;
                const int nb = n * 32 + lk;
                const int sw = n & 7;
                bfr[nt][0] = __float_as_uint(Bb[nb + ((c0 ^ sw) << 2)]);
                bfr[nt][1] = __float_as_uint(Bb[nb + ((c1 ^ sw) << 2)]);
            }
            unsigned afr[4][4];
#pragma unroll
            for (int mt = 0; mt < 4; mt++) {
                const int r0 = wm + mt * 16 + lm;
                const int b0 = r0 * 32 + lk;
                const int b1 = b0 + 256;          // (+8 rows) * 32
                const int sw = r0 & 7;
                afr[mt][0] = __float_as_uint(Ab[b0 + ((c0 ^ sw) << 2)]);
                afr[mt][1] = __float_as_uint(Ab[b1 + ((c0 ^ sw) << 2)]);
                afr[mt][2] = __float_as_uint(Ab[b0 + ((c1 ^ sw) << 2)]);
                afr[mt][3] = __float_as_uint(Ab[b1 + ((c1 ^ sw) << 2)]);
            }
#pragma unroll
            for (int mt = 0; mt < 4; mt++)
#pragma unroll
                for (int nt = 0; nt < 8; nt++)
                    mma_tf32(acc[mt][nt], afr[mt], bfr[nt]);
        }

        if (t + 2 < ktiles)
            asm volatile("cp.async.wait_group 1;\n" ::: "memory");
        else
            asm volatile("cp.async.wait_group 0;\n" ::: "memory");
        __syncthreads();
        if (++scomp == NSTAGE) scomp = 0;
    }

    // epilogue
#pragma unroll
    for (int mt = 0; mt < 4; mt++) {
        const int row = bm + wm + mt * 16 + lm;
#pragma unroll
        for (int nt = 0; nt < 8; nt++) {
            const int col = bn + wn + nt * 8 + lk * 2;
            const float2 bia = *reinterpret_cast<const float2*>(&bias[col]);
            float r0x = acc[mt][nt][0] + bia.x;
            float r0y = acc[mt][nt][1] + bia.y;
            float r1x = acc[mt][nt][2] + bia.x;
            float r1y = acc[mt][nt][3] + bia.y;
            if (RELU) {
                r0x = fmaxf(r0x, 0.f); r0y = fmaxf(r0y, 0.f);
                r1x = fmaxf(r1x, 0.f); r1y = fmaxf(r1y, 0.f);
            }
            if (TFOUT) {
                r0x = __uint_as_float(f2tf(r0x)); r0y = __uint_as_float(f2tf(r0y));
                r1x = __uint_as_float(f2tf(r1x)); r1y = __uint_as_float(f2tf(r1y));
            }
            *reinterpret_cast<float2*>(&C[(size_t)row * N + col])       = make_float2(r0x, r0y);
            *reinterpret_cast<float2*>(&C[(size_t)(row + 8) * N + col]) = make_float2(r1x, r1y);
        }
    }
}

// ---------------- block reductions ----------------
__device__ __forceinline__ float block_sum(float v, float* red) {
#pragma unroll
    for (int o = 16; o > 0; o >>= 1) v += __shfl_xor_sync(0xffffffffu, v, o);
    const int wid = threadIdx.x >> 5, lid = threadIdx.x & 31;
    const int nw = blockDim.x >> 5;
    if (lid == 0) red[wid] = v;
    __syncthreads();
    if (wid == 0) {
        v = (lid < nw) ? red[lid] : 0.f;
#pragma unroll
        for (int o = 16; o > 0; o >>= 1) v += __shfl_xor_sync(0xffffffffu, v, o);
        if (lid == 0) red[0] = v;
    }
    __syncthreads();
    float r = red[0];
    __syncthreads();
    return r;
}

__device__ __forceinline__ float block_max(float v, float* red) {
#pragma unroll
    for (int o = 16; o > 0; o >>= 1) v = fmaxf(v, __shfl_xor_sync(0xffffffffu, v, o));
    const int wid = threadIdx.x >> 5, lid = threadIdx.x & 31;
    const int nw = blockDim.x >> 5;
    if (lid == 0) red[wid] = v;
    __syncthreads();
    if (wid == 0) {
        v = (lid < nw) ? red[lid] : -3.4e38f;
#pragma unroll
        for (int o = 16; o > 0; o >>= 1) v = fmaxf(v, __shfl_xor_sync(0xffffffffu, v, o));
        if (lid == 0) red[0] = v;
    }
    __syncthreads();
    float r = red[0];
    __syncthreads();
    return r;
}

// ---------------- qp = q @ Wq + bq ----------------
__global__ void qp_kernel(const float* __restrict__ q, const float* __restrict__ Wq,
                          const float* __restrict__ bq)
{
    __shared__ float qs[DD];
    const int j = threadIdx.x;
    qs[j] = q[j];
    __syncthreads();
    float s = bq[j];
    for (int i = 0; i < DD; i++) s += qs[i] * Wq[i * DD + j];
    g_qp[j] = s;
}

// ---------------- wk_eff ----------------
__global__ void wk_eff_kernel(const float* __restrict__ Wk, const float* __restrict__ bk)
{
    __shared__ float qs[DD];
    const int i = threadIdx.x;
    qs[i] = g_qp[i];
    __syncthreads();
    const float* wr = Wk + (size_t)i * DD;
#pragma unroll
    for (int h = 0; h < NHEAD; h++) {
        float s = 0.f;
#pragma unroll
        for (int d = 0; d < HD; d++) s += wr[h * HD + d] * qs[h * HD + d];
        g_wk_eff[i * NHEAD + h] = s;
    }
    if (i < NHEAD) {
        float s = 0.f;
        for (int d = 0; d < HD; d++) s += bk[i * HD + d] * qs[i * HD + d];
        g_bk_eff[i] = s;
    }
}

// ---------------- scores ----------------
__global__ void scores_kernel()
{
    __shared__ float wk_s[DD][NHEAD];
    __shared__ float bk_s[NHEAD];
    const int tid  = threadIdx.x;
    const int warp = tid >> 5;
    const int lane = tid & 31;

    for (int i = tid; i < DD * NHEAD; i += 256)
        (&wk_s[0][0])[i] = g_wk_eff[i];
    if (tid < NHEAD) bk_s[tid] = g_bk_eff[tid];
    __syncthreads();

    const int row0 = blockIdx.x * 128;
    for (int it = 0; it < 16; it++) {
        const int row = row0 + it * 8 + warp;
        const float* hp = g_h + (size_t)row * DD;
        float acc[NHEAD];
#pragma unroll
        for (int h = 0; h < NHEAD; h++) acc[h] = 0.f;
#pragma unroll
        for (int c = 0; c < 16; c++) {
            const int i = lane + c * 32;
            const float hv = hp[i];
#pragma unroll
            for (int h = 0; h < NHEAD; h++) acc[h] += hv * wk_s[i][h];
        }
#pragma unroll
        for (int h = 0; h < NHEAD; h++) {
#pragma unroll
            for (int o = 16; o > 0; o >>= 1)
                acc[h] += __shfl_xor_sync(0xffffffffu, acc[h], o);
        }
        if (lane < NHEAD) {
            const int b = row >> 10;
            const int l = row & (LL - 1);
            float s = (acc[lane] + bk_s[lane]) * 0.125f;
            if (!g_valid[row]) s = -1e30f;
            g_s[(b * NHEAD + lane) * LL + l] = s;
        }
    }
}

// ---------------- softmax ----------------
__global__ void softmax_kernel()
{
    const int bh = blockIdx.x;
    const int tid = threadIdx.x;
    __shared__ float red[32];
    float* sp = g_s + (size_t)bh * LL;

    float v0 = sp[tid], v1 = sp[tid + 256], v2 = sp[tid + 512], v3 = sp[tid + 768];
    float mx = fmaxf(fmaxf(v0, v1), fmaxf(v2, v3));
    mx = block_max(mx, red);
    float e0 = __expf(v0 - mx), e1 = __expf(v1 - mx);
    float e2 = __expf(v2 - mx), e3 = __expf(v3 - mx);
    float sum = block_sum(e0 + e1 + e2 + e3, red);
    const float inv = 1.f / sum;
    sp[tid] = e0 * inv; sp[tid + 256] = e1 * inv;
    sp[tid + 512] = e2 * inv; sp[tid + 768] = e3 * inv;
}

// ---------------- hbar partials: grid (BB, 4), 256 l's per block ----------------
__global__ void __launch_bounds__(512)
hbar_kernel()
{
    const int b  = blockIdx.x;
    const int ch = blockIdx.y;      // 0..3
    const int d  = threadIdx.x;     // 512
    __shared__ float a_s[NHEAD][256];

    for (int i = d; i < NHEAD * 256; i += 512) {
        const int h = i >> 8, l = i & 255;
        a_s[h][l] = g_s[(size_t)(b * NHEAD + h) * LL + ch * 256 + l];
    }
    __syncthreads();

    float acc[NHEAD];
#pragma unroll
    for (int h = 0; h < NHEAD; h++) acc[h] = 0.f;

    const float* hp = g_h + ((size_t)b * LL + ch * 256) * DD + d;
#pragma unroll 4
    for (int l = 0; l < 256; l++) {
        const float hv = hp[(size_t)l * DD];
#pragma unroll
        for (int h = 0; h < NHEAD; h++) acc[h] += a_s[h][l] * hv;
    }
#pragma unroll
    for (int h = 0; h < NHEAD; h++)
        g_hbarp[(((size_t)ch * BB + b) * NHEAD + h) * DD + d] = acc[h];
}

// ---------------- ctx: sum partials, hbar @ Wv + bv ----------------
__global__ void ctx_kernel(const float* __restrict__ Wv, const float* __restrict__ bv)
{
    const int b = blockIdx.x;
    const int j = threadIdx.x;   // 512
    __shared__ float hb[NHEAD][DD];
    for (int i = j; i < NHEAD * DD; i += 512) {
        float s = 0.f;
#pragma unroll
        for (int c = 0; c < 4; c++)
            s += g_hbarp[((size_t)c * BB + b) * NHEAD * DD + i];
        (&hb[0][0])[i] = s;
    }
    __syncthreads();
    const int h = j >> 6;
    float s = bv[j];
    for (int i = 0; i < DD; i++) s += hb[h][i] * Wv[(size_t)i * DD + j];
    g_ctx[b * DD + j] = s;
}

// ---------------- pooled = ctx @ Wo + bo, then LayerNorm -> g_y ----------------
__global__ void __launch_bounds__(512)
pooled_ln_kernel(const float* __restrict__ Wo, const float* __restrict__ bo,
                 const float* __restrict__ ln_g, const float* __restrict__ ln_b)
{
    const int b = blockIdx.x;
    const int j = threadIdx.x;   // 512
    __shared__ float cx[DD];
    __shared__ float red[32];
    cx[j] = g_ctx[b * DD + j];
    __syncthreads();
    float s = bo[j];
    for (int i = 0; i < DD; i++) s += cx[i] * Wo[(size_t)i * DD + j];

    const float mu = block_sum(s, red) * (1.f / DD);
    float dv = s - mu;
    const float var = block_sum(dv * dv, red) * (1.f / DD);
    const float rstd = rsqrtf(var + 1e-5f);
    g_y[b * DD + j] = dv * rstd * ln_g[j] + ln_b[j];
}

// ---------------- head partials: grid (BB, 8) ----------------
__global__ void head1_kernel(const float* __restrict__ Wh1, const float* __restrict__ bh1,
                             const float* __restrict__ Wh2)
{
    const int b = blockIdx.x;
    const int sl = blockIdx.y;      // 0..7
    const int tid = threadIdx.x;    // 256
    __shared__ float y[DD];
    __shared__ float red[32];

    y[tid]       = g_y[b * DD + tid];
    y[tid + 256] = g_y[b * DD + tid + 256];
    __syncthreads();

    const int j = sl * 256 + tid;
    float t = bh1[j];
    for (int i = 0; i < DD; i++) t += y[i] * Wh1[(size_t)i * HH + j];
    float p = fmaxf(t, 0.f) * Wh2[j];
    const float tot = block_sum(p, red);
    if (tid == 0) g_hpart[b * 8 + sl] = tot;
}

__global__ void head2_kernel(const float* __restrict__ bh2, float* __restrict__ out)
{
    const int b = threadIdx.x;   // 64
    float s = bh2[0];
#pragma unroll
    for (int i = 0; i < 8; i++) s += g_hpart[b * 8 + i];
    out[b] = s;
}

// ---------------- launcher ----------------
extern "C" void kernel_launch(void* const* d_in, const int* in_sizes, int n_in,
                              void* d_out, int out_size)
{
    const int*   mut  = (const int*)d_in[0];
    const int*   offs = (const int*)d_in[1];
    const float* emb  = (const float*)d_in[2];
    const float* W1   = (const float*)d_in[3];
    const float* b1   = (const float*)d_in[4];
    const float* W2   = (const float*)d_in[5];
    const float* b2   = (const float*)d_in[6];
    const float* q    = (const float*)d_in[7];
    const float* Wq   = (const float*)d_in[8];
    const float* bq   = (const float*)d_in[9];
    const float* Wk   = (const float*)d_in[10];
    const float* bk   = (const float*)d_in[11];
    const float* Wv   = (const float*)d_in[12];
    const float* bv   = (const float*)d_in[13];
    const float* Wo   = (const float*)d_in[14];
    const float* bo   = (const float*)d_in[15];
    const float* ln_g = (const float*)d_in[16];
    const float* ln_b = (const float*)d_in[17];
    const float* Wh1  = (const float*)d_in[18];
    const float* bh1  = (const float*)d_in[19];
    const float* Wh2  = (const float*)d_in[20];
    const float* bh2  = (const float*)d_in[21];
    float* out = (float*)d_out;

    void *p_z, *p_hid, *p_h, *p_w1t, *p_w2t;
    cudaGetSymbolAddress(&p_z,   g_z);
    cudaGetSymbolAddress(&p_hid, g_hid);
    cudaGetSymbolAddress(&p_h,   g_h);
    cudaGetSymbolAddress(&p_w1t, g_w1t);
    cudaGetSymbolAddress(&p_w2t, g_w2t);
    float* zf  = (float*)p_z;
    float* hid = (float*)p_hid;
    float* hbf = (float*)p_h;
    float* w1t = (float*)p_w1t;
    float* w2t = (float*)p_w2t;

    cudaFuncSetAttribute(tf32_gemm_kernel<true, true>,
                         cudaFuncAttributeMaxDynamicSharedMemorySize, GSMEM);
    cudaFuncSetAttribute(tf32_gemm_kernel<false, false>,
                         cudaFuncAttributeMaxDynamicSharedMemorySize, GSMEM);

    // 0) weight transpose + tf32 round
    wttf_kernel<<<dim3(HH / 32, DD / 32), dim3(32, 8)>>>(W1, w1t, DD, HH);
    wttf_kernel<<<dim3(DD / 32, HH / 32), dim3(32, 8)>>>(W2, w2t, HH, DD);

    // 1) token gather + mask; gathered emb -> tf32
    gather_tok_kernel<<<TOTAL / 256, 256>>>(mut, offs);
    ztf_kernel<<<(TOTAL * 128) / 256, 256>>>(emb);

    // 2) hid = tf32(relu(z @ W1 + b1))   [65536 x 2048], K=512
    tf32_gemm_kernel<true, true><<<dim3(HH / BN, TOTAL / BM), 256, GSMEM>>>(
        zf, w1t, b1, hid, HH, DD);

    // 3) h = hid @ W2 + b2               [65536 x 512], K=2048
    tf32_gemm_kernel<false, false><<<dim3(DD / BN, TOTAL / BM), 256, GSMEM>>>(
        hid, w2t, b2, hbf, DD, HH);

    // 4) qp, wk_eff
    qp_kernel<<<1, DD>>>(q, Wq, bq);
    wk_eff_kernel<<<1, DD>>>(Wk, bk);

    // 5) scores + softmax
    scores_kernel<<<TOTAL / 128, 256>>>();
    softmax_kernel<<<BB * NHEAD, 256>>>();

    // 6) hbar partials, ctx
    hbar_kernel<<<dim3(BB, 4), 512>>>();
    ctx_kernel<<<BB, DD>>>(Wv, bv);

    // 7) pooled + LN
    pooled_ln_kernel<<<BB, DD>>>(Wo, bo, ln_g, ln_b);

    // 8) head
    head1_kernel<<<dim3(BB, 8), 256>>>(Wh1, bh1, Wh2);
    head2_kernel<<<1, BB>>>(bh2, out);
}

// round 7
// speedup vs baseline: 5.8512x; 1.4691x over previous
#include <cuda_runtime.h>
#include <cuda_fp16.h>
#include <cstdint>

#define BB 64
#define LL 1024
#define TOTAL (BB * LL)
#define DD 512
#define HH 2048
#define NHEAD 8
#define HD 64

// ---------------- scratch (static device globals; no allocation) ----------------
__device__ __half g_zh  [(size_t)TOTAL * DD];   // 64 MiB  gathered emb fp16
__device__ __half g_hidh[(size_t)TOTAL * HH];   // 256 MiB hidden fp16
__device__ __half g_w1t [(size_t)HH * DD];      // W1^T [2048][512] fp16
__device__ __half g_w2t [(size_t)DD * HH];      // W2^T [512][2048] fp16
__device__ float g_h  [(size_t)TOTAL * DD];     // 128 MiB fp32
__device__ float g_s  [BB * NHEAD * LL];
__device__ float g_hbarp[4 * BB * NHEAD * DD];
__device__ float g_qp [DD];
__device__ float g_wk_eff[DD * NHEAD];
__device__ float g_bk_eff[NHEAD];
__device__ float g_ctx[BB * DD];
__device__ float g_y  [BB * DD];
__device__ float g_hpart[BB * 8];
__device__ int   g_tok[TOTAL];
__device__ unsigned char g_valid[TOTAL];

// ---------------- helpers ----------------
__device__ __forceinline__ unsigned pack_h2(float lo, float hi) {
    __half2 p = __floats2half2_rn(lo, hi);   // .x = lo (low address)
    return *reinterpret_cast<unsigned*>(&p);
}

__device__ __forceinline__ void mma_f16(float* c, const unsigned* a, const unsigned* b) {
    asm volatile(
        "mma.sync.aligned.m16n8k16.row.col.f32.f16.f16.f32 "
        "{%0,%1,%2,%3}, {%4,%5,%6,%7}, {%8,%9}, {%0,%1,%2,%3};\n"
        : "+f"(c[0]), "+f"(c[1]), "+f"(c[2]), "+f"(c[3])
        : "r"(a[0]), "r"(a[1]), "r"(a[2]), "r"(a[3]), "r"(b[0]), "r"(b[1]));
}

__device__ __forceinline__ void cp16(void* smem_dst, const void* gsrc) {
    unsigned sdst = (unsigned)__cvta_generic_to_shared(smem_dst);
    asm volatile("cp.async.cg.shared.global [%0], [%1], 16;\n"
                 :: "r"(sdst), "l"(gsrc) : "memory");
}

// ---------------- token gather / mask ----------------
__global__ void gather_tok_kernel(const int* __restrict__ mut,
                                  const int* __restrict__ offs)
{
    int t = blockIdx.x * blockDim.x + threadIdx.x;
    if (t >= TOTAL) return;
    int b = t >> 10;
    int l = t & (LL - 1);
    int s = offs[b];
    int e = offs[b + 1];
    bool ok = l < (e - s);
    g_tok[t]   = ok ? mut[s + l] : 0;
    g_valid[t] = ok ? 1 : 0;
}

// ---------------- pre-pass: gathered emb -> fp16 ----------------
__global__ void zh_kernel(const float* __restrict__ emb)
{
    int gid = blockIdx.x * blockDim.x + threadIdx.x;   // TOTAL*64 threads
    int r = gid >> 6;
    int c = (gid & 63) << 3;
    int t = g_tok[r];
    const float4* src = reinterpret_cast<const float4*>(emb + (size_t)t * DD + c);
    float4 v0 = src[0], v1 = src[1];
    uint4 o;
    o.x = pack_h2(v0.x, v0.y);
    o.y = pack_h2(v0.z, v0.w);
    o.z = pack_h2(v1.x, v1.y);
    o.w = pack_h2(v1.z, v1.w);
    *reinterpret_cast<uint4*>(g_zh + (size_t)r * DD + c) = o;
}

// ---------------- pre-pass: W [K][N] fp32 -> W^T [N][K] fp16 ----------------
__global__ void wtrans_kernel(const float* __restrict__ W, __half* __restrict__ WT,
                              int K, int N)
{
    __shared__ float tile[32][33];
    const int k0 = blockIdx.y * 32, n0 = blockIdx.x * 32;
    const int tx = threadIdx.x, ty = threadIdx.y;  // 32 x 8
#pragma unroll
    for (int i = 0; i < 4; i++)
        tile[ty + i * 8][tx] = W[(size_t)(k0 + ty + i * 8) * N + n0 + tx];
    __syncthreads();
#pragma unroll
    for (int i = 0; i < 4; i++)
        WT[(size_t)(n0 + ty + i * 8) * K + k0 + tx] = __float2half_rn(tile[tx][ty + i * 8]);
}

// ---------------- fp16 tensor-core GEMM ----------------
// C[M,N] = op(A[M,K]_f16 @ B^T[N,K]_f16 + bias). Block 128x128, BK=64.
// Smem rows = 128 B (64 halves), XOR-8 swizzle on 16B chunks -> conflict-free.
#define BK 64
#define ATILE (128 * BK)   // halves per buffer (A or B)

template<bool HOUT, bool RELU>
__global__ void __launch_bounds__(256, 2)
f16_gemm_kernel(const __half* __restrict__ A,
                const __half* __restrict__ Bt,
                const float* __restrict__ bias, void* __restrict__ Cv,
                int N, int K)
{
    extern __shared__ __align__(16) __half sm[];
    __half* As = sm;                 // [2][128][64]
    __half* Bs = sm + 2 * ATILE;     // [2][128][64]

    const int tid  = threadIdx.x;
    const int bm   = blockIdx.y * 128;
    const int bn   = blockIdx.x * 128;
    const int warp = tid >> 5;
    const int lane = tid & 31;
    const int lm   = lane >> 2;
    const int lk   = lane & 3;
    const int wm   = (warp >> 2) * 64;
    const int wn   = (warp & 3) * 32;

    // copy mapping: thread -> (row, 16B chunk); 32 rows per pass, 4 passes
    const int lrow = tid >> 3;          // 0..31
    const int lchk = tid & 7;           // 0..7

    const __half* aptr[4];
    const __half* bptr[4];
    int adst[4];
#pragma unroll
    for (int p = 0; p < 4; p++) {
        const int r = lrow + p * 32;
        aptr[p] = A  + (size_t)(bm + r) * K + lchk * 8;
        bptr[p] = Bt + (size_t)(bn + r) * K + lchk * 8;
        adst[p] = r * BK + ((lchk ^ (r & 7)) * 8);
    }

    float acc[4][4][4];
#pragma unroll
    for (int mt = 0; mt < 4; mt++)
#pragma unroll
        for (int nt = 0; nt < 4; nt++)
#pragma unroll
            for (int r = 0; r < 4; r++) acc[mt][nt][r] = 0.f;

    // prologue
#pragma unroll
    for (int p = 0; p < 4; p++) cp16(As + adst[p], aptr[p]);
#pragma unroll
    for (int p = 0; p < 4; p++) cp16(Bs + adst[p], bptr[p]);
    asm volatile("cp.async.commit_group;\n" ::: "memory");
    asm volatile("cp.async.wait_group 0;\n" ::: "memory");
    __syncthreads();

    const int ktiles = K / BK;
    int buf = 0;
    for (int t = 0; t < ktiles; t++) {
        if (t + 1 < ktiles) {
            const int kt = (t + 1) * BK;
            __half* Ad = As + (buf ^ 1) * ATILE;
            __half* Bd = Bs + (buf ^ 1) * ATILE;
#pragma unroll
            for (int p = 0; p < 4; p++) cp16(Ad + adst[p], aptr[p] + kt);
#pragma unroll
            for (int p = 0; p < 4; p++) cp16(Bd + adst[p], bptr[p] + kt);
            asm volatile("cp.async.commit_group;\n" ::: "memory");
        }

        const __half* Ab = As + buf * ATILE;
        const __half* Bb = Bs + buf * ATILE;
#pragma unroll
        for (int kk = 0; kk < 4; kk++) {
            const int c0 = 2 * kk, c1 = 2 * kk + 1;
            unsigned bfrag[4][2];
#pragma unroll
            for (int nt = 0; nt < 4; nt++) {
                const int n  = wn + nt * 8 + lm;
                const int nb = n * BK + lk * 2;
                const int sw = n & 7;
                bfrag[nt][0] = *reinterpret_cast<const unsigned*>(Bb + nb + ((c0 ^ sw) * 8));
                bfrag[nt][1] = *reinterpret_cast<const unsigned*>(Bb + nb + ((c1 ^ sw) * 8));
            }
            unsigned afrag[4][4];
#pragma unroll
            for (int mt = 0; mt < 4; mt++) {
                const int r0 = wm + mt * 16 + lm;
                const int r1 = r0 + 8;
                const int sw = r0 & 7;
                const int o0 = r0 * BK + lk * 2;
                const int o1 = r1 * BK + lk * 2;
                afrag[mt][0] = *reinterpret_cast<const unsigned*>(Ab + o0 + ((c0 ^ sw) * 8));
                afrag[mt][1] = *reinterpret_cast<const unsigned*>(Ab + o1 + ((c0 ^ sw) * 8));
                afrag[mt][2] = *reinterpret_cast<const unsigned*>(Ab + o0 + ((c1 ^ sw) * 8));
                afrag[mt][3] = *reinterpret_cast<const unsigned*>(Ab + o1 + ((c1 ^ sw) * 8));
            }
#pragma unroll
            for (int mt = 0; mt < 4; mt++)
#pragma unroll
                for (int nt = 0; nt < 4; nt++)
                    mma_f16(acc[mt][nt], afrag[mt], bfrag[nt]);
        }

        if (t + 1 < ktiles)
            asm volatile("cp.async.wait_group 0;\n" ::: "memory");
        __syncthreads();
        buf ^= 1;
    }

    // epilogue
#pragma unroll
    for (int mt = 0; mt < 4; mt++) {
        const int row = bm + wm + mt * 16 + lm;
#pragma unroll
        for (int nt = 0; nt < 4; nt++) {
            const int col = bn + wn + nt * 8 + lk * 2;
            const float2 bia = *reinterpret_cast<const float2*>(&bias[col]);
            float r0x = acc[mt][nt][0] + bia.x;
            float r0y = acc[mt][nt][1] + bia.y;
            float r1x = acc[mt][nt][2] + bia.x;
            float r1y = acc[mt][nt][3] + bia.y;
            if (RELU) {
                r0x = fmaxf(r0x, 0.f); r0y = fmaxf(r0y, 0.f);
                r1x = fmaxf(r1x, 0.f); r1y = fmaxf(r1y, 0.f);
            }
            if (HOUT) {
                __half* C = (__half*)Cv;
                *reinterpret_cast<unsigned*>(C + (size_t)row * N + col)       = pack_h2(r0x, r0y);
                *reinterpret_cast<unsigned*>(C + (size_t)(row + 8) * N + col) = pack_h2(r1x, r1y);
            } else {
                float* C = (float*)Cv;
                *reinterpret_cast<float2*>(C + (size_t)row * N + col)       = make_float2(r0x, r0y);
                *reinterpret_cast<float2*>(C + (size_t)(row + 8) * N + col) = make_float2(r1x, r1y);
            }
        }
    }
}

// ---------------- block reductions ----------------
__device__ __forceinline__ float block_sum(float v, float* red) {
#pragma unroll
    for (int o = 16; o > 0; o >>= 1) v += __shfl_xor_sync(0xffffffffu, v, o);
    const int wid = threadIdx.x >> 5, lid = threadIdx.x & 31;
    const int nw = blockDim.x >> 5;
    if (lid == 0) red[wid] = v;
    __syncthreads();
    if (wid == 0) {
        v = (lid < nw) ? red[lid] : 0.f;
#pragma unroll
        for (int o = 16; o > 0; o >>= 1) v += __shfl_xor_sync(0xffffffffu, v, o);
        if (lid == 0) red[0] = v;
    }
    __syncthreads();
    float r = red[0];
    __syncthreads();
    return r;
}

__device__ __forceinline__ float block_max(float v, float* red) {
#pragma unroll
    for (int o = 16; o > 0; o >>= 1) v = fmaxf(v, __shfl_xor_sync(0xffffffffu, v, o));
    const int wid = threadIdx.x >> 5, lid = threadIdx.x & 31;
    const int nw = blockDim.x >> 5;
    if (lid == 0) red[wid] = v;
    __syncthreads();
    if (wid == 0) {
        v = (lid < nw) ? red[lid] : -3.4e38f;
#pragma unroll
        for (int o = 16; o > 0; o >>= 1) v = fmaxf(v, __shfl_xor_sync(0xffffffffu, v, o));
        if (lid == 0) red[0] = v;
    }
    __syncthreads();
    float r = red[0];
    __syncthreads();
    return r;
}

// ---------------- qp = q @ Wq + bq ----------------
__global__ void qp_kernel(const float* __restrict__ q, const float* __restrict__ Wq,
                          const float* __restrict__ bq)
{
    __shared__ float qs[DD];
    const int j = threadIdx.x;
    qs[j] = q[j];
    __syncthreads();
    float s = bq[j];
    for (int i = 0; i < DD; i++) s += qs[i] * Wq[i * DD + j];
    g_qp[j] = s;
}

// ---------------- wk_eff ----------------
__global__ void wk_eff_kernel(const float* __restrict__ Wk, const float* __restrict__ bk)
{
    __shared__ float qs[DD];
    const int i = threadIdx.x;
    qs[i] = g_qp[i];
    __syncthreads();
    const float* wr = Wk + (size_t)i * DD;
#pragma unroll
    for (int h = 0; h < NHEAD; h++) {
        float s = 0.f;
#pragma unroll
        for (int d = 0; d < HD; d++) s += wr[h * HD + d] * qs[h * HD + d];
        g_wk_eff[i * NHEAD + h] = s;
    }
    if (i < NHEAD) {
        float s = 0.f;
        for (int d = 0; d < HD; d++) s += bk[i * HD + d] * qs[i * HD + d];
        g_bk_eff[i] = s;
    }
}

// ---------------- scores ----------------
__global__ void scores_kernel()
{
    __shared__ float wk_s[DD][NHEAD];
    __shared__ float bk_s[NHEAD];
    const int tid  = threadIdx.x;
    const int warp = tid >> 5;
    const int lane = tid & 31;

    for (int i = tid; i < DD * NHEAD; i += 256)
        (&wk_s[0][0])[i] = g_wk_eff[i];
    if (tid < NHEAD) bk_s[tid] = g_bk_eff[tid];
    __syncthreads();

    const int row0 = blockIdx.x * 128;
    for (int it = 0; it < 16; it++) {
        const int row = row0 + it * 8 + warp;
        const float* hp = g_h + (size_t)row * DD;
        float acc[NHEAD];
#pragma unroll
        for (int h = 0; h < NHEAD; h++) acc[h] = 0.f;
#pragma unroll
        for (int c = 0; c < 16; c++) {
            const int i = lane + c * 32;
            const float hv = hp[i];
#pragma unroll
            for (int h = 0; h < NHEAD; h++) acc[h] += hv * wk_s[i][h];
        }
#pragma unroll
        for (int h = 0; h < NHEAD; h++) {
#pragma unroll
            for (int o = 16; o > 0; o >>= 1)
                acc[h] += __shfl_xor_sync(0xffffffffu, acc[h], o);
        }
        if (lane < NHEAD) {
            const int b = row >> 10;
            const int l = row & (LL - 1);
            float s = (acc[lane] + bk_s[lane]) * 0.125f;
            if (!g_valid[row]) s = -1e30f;
            g_s[(b * NHEAD + lane) * LL + l] = s;
        }
    }
}

// ---------------- softmax ----------------
__global__ void softmax_kernel()
{
    const int bh = blockIdx.x;
    const int tid = threadIdx.x;
    __shared__ float red[32];
    float* sp = g_s + (size_t)bh * LL;

    float v0 = sp[tid], v1 = sp[tid + 256], v2 = sp[tid + 512], v3 = sp[tid + 768];
    float mx = fmaxf(fmaxf(v0, v1), fmaxf(v2, v3));
    mx = block_max(mx, red);
    float e0 = __expf(v0 - mx), e1 = __expf(v1 - mx);
    float e2 = __expf(v2 - mx), e3 = __expf(v3 - mx);
    float sum = block_sum(e0 + e1 + e2 + e3, red);
    const float inv = 1.f / sum;
    sp[tid] = e0 * inv; sp[tid + 256] = e1 * inv;
    sp[tid + 512] = e2 * inv; sp[tid + 768] = e3 * inv;
}

// ---------------- hbar partials: grid (BB, 4) ----------------
__global__ void __launch_bounds__(512)
hbar_kernel()
{
    const int b  = blockIdx.x;
    const int ch = blockIdx.y;
    const int d  = threadIdx.x;
    __shared__ float a_s[NHEAD][256];

    for (int i = d; i < NHEAD * 256; i += 512) {
        const int h = i >> 8, l = i & 255;
        a_s[h][l] = g_s[(size_t)(b * NHEAD + h) * LL + ch * 256 + l];
    }
    __syncthreads();

    float acc[NHEAD];
#pragma unroll
    for (int h = 0; h < NHEAD; h++) acc[h] = 0.f;

    const float* hp = g_h + ((size_t)b * LL + ch * 256) * DD + d;
#pragma unroll 4
    for (int l = 0; l < 256; l++) {
        const float hv = hp[(size_t)l * DD];
#pragma unroll
        for (int h = 0; h < NHEAD; h++) acc[h] += a_s[h][l] * hv;
    }
#pragma unroll
    for (int h = 0; h < NHEAD; h++)
        g_hbarp[(((size_t)ch * BB + b) * NHEAD + h) * DD + d] = acc[h];
}

// ---------------- ctx ----------------
__global__ void ctx_kernel(const float* __restrict__ Wv, const float* __restrict__ bv)
{
    const int b = blockIdx.x;
    const int j = threadIdx.x;
    __shared__ float hb[NHEAD][DD];
    for (int i = j; i < NHEAD * DD; i += 512) {
        float s = 0.f;
#pragma unroll
        for (int c = 0; c < 4; c++)
            s += g_hbarp[((size_t)c * BB + b) * NHEAD * DD + i];
        (&hb[0][0])[i] = s;
    }
    __syncthreads();
    const int h = j >> 6;
    float s = bv[j];
    for (int i = 0; i < DD; i++) s += hb[h][i] * Wv[(size_t)i * DD + j];
    g_ctx[b * DD + j] = s;
}

// ---------------- pooled + LN ----------------
__global__ void __launch_bounds__(512)
pooled_ln_kernel(const float* __restrict__ Wo, const float* __restrict__ bo,
                 const float* __restrict__ ln_g, const float* __restrict__ ln_b)
{
    const int b = blockIdx.x;
    const int j = threadIdx.x;
    __shared__ float cx[DD];
    __shared__ float red[32];
    cx[j] = g_ctx[b * DD + j];
    __syncthreads();
    float s = bo[j];
    for (int i = 0; i < DD; i++) s += cx[i] * Wo[(size_t)i * DD + j];

    const float mu = block_sum(s, red) * (1.f / DD);
    float dv = s - mu;
    const float var = block_sum(dv * dv, red) * (1.f / DD);
    const float rstd = rsqrtf(var + 1e-5f);
    g_y[b * DD + j] = dv * rstd * ln_g[j] + ln_b[j];
}

// ---------------- head ----------------
__global__ void head1_kernel(const float* __restrict__ Wh1, const float* __restrict__ bh1,
                             const float* __restrict__ Wh2)
{
    const int b = blockIdx.x;
    const int sl = blockIdx.y;
    const int tid = threadIdx.x;
    __shared__ float y[DD];
    __shared__ float red[32];

    y[tid]       = g_y[b * DD + tid];
    y[tid + 256] = g_y[b * DD + tid + 256];
    __syncthreads();

    const int j = sl * 256 + tid;
    float t = bh1[j];
    for (int i = 0; i < DD; i++) t += y[i] * Wh1[(size_t)i * HH + j];
    float p = fmaxf(t, 0.f) * Wh2[j];
    const float tot = block_sum(p, red);
    if (tid == 0) g_hpart[b * 8 + sl] = tot;
}

__global__ void head2_kernel(const float* __restrict__ bh2, float* __restrict__ out)
{
    const int b = threadIdx.x;
    float s = bh2[0];
#pragma unroll
    for (int i = 0; i < 8; i++) s += g_hpart[b * 8 + i];
    out[b] = s;
}

// ---------------- launcher ----------------
extern "C" void kernel_launch(void* const* d_in, const int* in_sizes, int n_in,
                              void* d_out, int out_size)
{
    const int*   mut  = (const int*)d_in[0];
    const int*   offs = (const int*)d_in[1];
    const float* emb  = (const float*)d_in[2];
    const float* W1   = (const float*)d_in[3];
    const float* b1   = (const float*)d_in[4];
    const float* W2   = (const float*)d_in[5];
    const float* b2   = (const float*)d_in[6];
    const float* q    = (const float*)d_in[7];
    const float* Wq   = (const float*)d_in[8];
    const float* bq   = (const float*)d_in[9];
    const float* Wk   = (const float*)d_in[10];
    const float* bk   = (const float*)d_in[11];
    const float* Wv   = (const float*)d_in[12];
    const float* bv   = (const float*)d_in[13];
    const float* Wo   = (const float*)d_in[14];
    const float* bo   = (const float*)d_in[15];
    const float* ln_g = (const float*)d_in[16];
    const float* ln_b = (const float*)d_in[17];
    const float* Wh1  = (const float*)d_in[18];
    const float* bh1  = (const float*)d_in[19];
    const float* Wh2  = (const float*)d_in[20];
    const float* bh2  = (const float*)d_in[21];
    float* out = (float*)d_out;

    void *p_zh, *p_hidh, *p_w1t, *p_w2t, *p_h;
    cudaGetSymbolAddress(&p_zh,   g_zh);
    cudaGetSymbolAddress(&p_hidh, g_hidh);
    cudaGetSymbolAddress(&p_w1t,  g_w1t);
    cudaGetSymbolAddress(&p_w2t,  g_w2t);
    cudaGetSymbolAddress(&p_h,    g_h);
    __half* zh   = (__half*)p_zh;
    __half* hidh = (__half*)p_hidh;
    __half* w1t  = (__half*)p_w1t;
    __half* w2t  = (__half*)p_w2t;
    float*  hbf  = (float*)p_h;

    const int smem_bytes = 4 * ATILE * 2;  // 65536 B (2 bufs x (A+B) x 2B)
    cudaFuncSetAttribute(f16_gemm_kernel<true, true>,
                         cudaFuncAttributeMaxDynamicSharedMemorySize, smem_bytes);
    cudaFuncSetAttribute(f16_gemm_kernel<false, false>,
                         cudaFuncAttributeMaxDynamicSharedMemorySize, smem_bytes);

    // 0) weight transpose + fp16 convert
    wtrans_kernel<<<dim3(HH / 32, DD / 32), dim3(32, 8)>>>(W1, w1t, DD, HH);
    wtrans_kernel<<<dim3(DD / 32, HH / 32), dim3(32, 8)>>>(W2, w2t, HH, DD);

    // 1) token gather + mask; gathered emb -> fp16
    gather_tok_kernel<<<TOTAL / 256, 256>>>(mut, offs);
    zh_kernel<<<(TOTAL * 64) / 256, 256>>>(emb);

    // 2) hidh = f16(relu(zh @ W1 + b1))   [65536 x 2048], K=512
    f16_gemm_kernel<true, true><<<dim3(HH / 128, TOTAL / 128), 256, smem_bytes>>>(
        zh, w1t, b1, hidh, HH, DD);

    // 3) h = hidh @ W2 + b2 (fp32 out)    [65536 x 512], K=2048
    f16_gemm_kernel<false, false><<<dim3(DD / 128, TOTAL / 128), 256, smem_bytes>>>(
        hidh, w2t, b2, hbf, DD, HH);

    // 4) qp, wk_eff
    qp_kernel<<<1, DD>>>(q, Wq, bq);
    wk_eff_kernel<<<1, DD>>>(Wk, bk);

    // 5) scores + softmax
    scores_kernel<<<TOTAL / 128, 256>>>();
    softmax_kernel<<<BB * NHEAD, 256>>>();

    // 6) hbar partials, ctx
    hbar_kernel<<<dim3(BB, 4), 512>>>();
    ctx_kernel<<<BB, DD>>>(Wv, bv);

    // 7) pooled + LN
    pooled_ln_kernel<<<BB, DD>>>(Wo, bo, ln_g, ln_b);

    // 8) head
    head1_kernel<<<dim3(BB, 8), 256>>>(Wh1, bh1, Wh2);
    head2_kernel<<<1, BB>>>(bh2, out);
}

// round 8
// speedup vs baseline: 6.3960x; 1.0931x over previous
#include <cuda_runtime.h>
#include <cuda_fp16.h>
#include <cstdint>

#define BB 64
#define LL 1024
#define TOTAL (BB * LL)
#define DD 512
#define HH 2048
#define NHEAD 8
#define HD 64

// ---------------- scratch (static device globals; no allocation) ----------------
__device__ __half g_zh  [(size_t)TOTAL * DD];   // 64 MiB  gathered emb fp16
__device__ __half g_hidh[(size_t)TOTAL * HH];   // 256 MiB hidden fp16
__device__ __half g_w1t [(size_t)HH * DD];      // W1^T [2048][512] fp16
__device__ __half g_w2t [(size_t)DD * HH];      // W2^T [512][2048] fp16
__device__ float g_h  [(size_t)TOTAL * DD];     // 128 MiB fp32
__device__ float g_s  [BB * NHEAD * LL];
__device__ float g_hbarp[4 * BB * NHEAD * DD];
__device__ float g_qp [DD];
__device__ float g_wk_eff[DD * NHEAD];
__device__ float g_bk_eff[NHEAD];
__device__ float g_ctx[BB * DD];
__device__ float g_y  [BB * DD];
__device__ float g_hpart[BB * 8];
__device__ int   g_tok[TOTAL];
__device__ unsigned char g_valid[TOTAL];

// ---------------- helpers ----------------
__device__ __forceinline__ unsigned pack_h2(float lo, float hi) {
    __half2 p = __floats2half2_rn(lo, hi);
    return *reinterpret_cast<unsigned*>(&p);
}

__device__ __forceinline__ void mma_f16(float* c, const unsigned* a, const unsigned* b) {
    asm volatile(
        "mma.sync.aligned.m16n8k16.row.col.f32.f16.f16.f32 "
        "{%0,%1,%2,%3}, {%4,%5,%6,%7}, {%8,%9}, {%0,%1,%2,%3};\n"
        : "+f"(c[0]), "+f"(c[1]), "+f"(c[2]), "+f"(c[3])
        : "r"(a[0]), "r"(a[1]), "r"(a[2]), "r"(a[3]), "r"(b[0]), "r"(b[1]));
}

__device__ __forceinline__ void ldsm_x4(unsigned* r, unsigned addr) {
    asm volatile("ldmatrix.sync.aligned.m8n8.x4.shared.b16 {%0,%1,%2,%3}, [%4];"
                 : "=r"(r[0]), "=r"(r[1]), "=r"(r[2]), "=r"(r[3]) : "r"(addr));
}

__device__ __forceinline__ void ldsm_x2(unsigned* r, unsigned addr) {
    asm volatile("ldmatrix.sync.aligned.m8n8.x2.shared.b16 {%0,%1}, [%2];"
                 : "=r"(r[0]), "=r"(r[1]) : "r"(addr));
}

__device__ __forceinline__ void cp16(void* smem_dst, const void* gsrc) {
    unsigned sdst = (unsigned)__cvta_generic_to_shared(smem_dst);
    asm volatile("cp.async.cg.shared.global [%0], [%1], 16;\n"
                 :: "r"(sdst), "l"(gsrc) : "memory");
}

#define CP_COMMIT() asm volatile("cp.async.commit_group;" ::: "memory")

// ---------------- token gather / mask ----------------
__global__ void gather_tok_kernel(const int* __restrict__ mut,
                                  const int* __restrict__ offs)
{
    int t = blockIdx.x * blockDim.x + threadIdx.x;
    if (t >= TOTAL) return;
    int b = t >> 10;
    int l = t & (LL - 1);
    int s = offs[b];
    int e = offs[b + 1];
    bool ok = l < (e - s);
    g_tok[t]   = ok ? mut[s + l] : 0;
    g_valid[t] = ok ? 1 : 0;
}

// ---------------- pre-pass: gathered emb -> fp16 ----------------
__global__ void zh_kernel(const float* __restrict__ emb)
{
    int gid = blockIdx.x * blockDim.x + threadIdx.x;
    int r = gid >> 6;
    int c = (gid & 63) << 3;
    int t = g_tok[r];
    const float4* src = reinterpret_cast<const float4*>(emb + (size_t)t * DD + c);
    float4 v0 = src[0], v1 = src[1];
    uint4 o;
    o.x = pack_h2(v0.x, v0.y);
    o.y = pack_h2(v0.z, v0.w);
    o.z = pack_h2(v1.x, v1.y);
    o.w = pack_h2(v1.z, v1.w);
    *reinterpret_cast<uint4*>(g_zh + (size_t)r * DD + c) = o;
}

// ---------------- pre-pass: W [K][N] fp32 -> W^T [N][K] fp16 ----------------
__global__ void wtrans_kernel(const float* __restrict__ W, __half* __restrict__ WT,
                              int K, int N)
{
    __shared__ float tile[32][33];
    const int k0 = blockIdx.y * 32, n0 = blockIdx.x * 32;
    const int tx = threadIdx.x, ty = threadIdx.y;
#pragma unroll
    for (int i = 0; i < 4; i++)
        tile[ty + i * 8][tx] = W[(size_t)(k0 + ty + i * 8) * N + n0 + tx];
    __syncthreads();
#pragma unroll
    for (int i = 0; i < 4; i++)
        WT[(size_t)(n0 + ty + i * 8) * K + k0 + tx] = __float2half_rn(tile[tx][ty + i * 8]);
}

// ---------------- fp16 tensor-core GEMM, ldmatrix + 3-stage cp.async -----------
// C[M,N] = op(A[M,K]_f16 @ B^T[N,K]_f16 + bias). Block 128x128, BK=64.
// Smem rows = 128 B (64 halves), XOR-8 swizzle on 16B chunks.
#define BK 64
#define ATILE 8192            // halves: 128 rows * 64
#define STAGE (2 * ATILE)     // A tile + B tile
#define NSTG 3
#define GSMEM (NSTG * STAGE * 2)   // 98304 B

template<bool HOUT, bool RELU>
__global__ void __launch_bounds__(256, 2)
f16_gemm_kernel(const __half* __restrict__ A,
                const __half* __restrict__ Bt,
                const float* __restrict__ bias, void* __restrict__ Cv,
                int N, int K)
{
    extern __shared__ __align__(16) __half sm[];

    const int tid  = threadIdx.x;
    const int bm   = blockIdx.y * 128;
    const int bn   = blockIdx.x * 128;
    const int warp = tid >> 5;
    const int lane = tid & 31;
    const int lm   = lane >> 2;
    const int lk   = lane & 3;
    const int wm   = (warp >> 2) * 64;
    const int wn   = (warp & 3) * 32;

    const unsigned smem_b = (unsigned)__cvta_generic_to_shared(sm);

    // ---- copy mapping: thread -> (row, 16B chunk); 32 rows/pass, 4 passes ----
    const int lrow = tid >> 3;
    const int lchk = tid & 7;
    const __half* aptr[4];
    const __half* bptr[4];
    int adst[4];
#pragma unroll
    for (int p = 0; p < 4; p++) {
        const int r = lrow + p * 32;
        aptr[p] = A  + (size_t)(bm + r) * K + lchk * 8;
        bptr[p] = Bt + (size_t)(bn + r) * K + lchk * 8;
        adst[p] = r * BK + ((lchk ^ (r & 7)) * 8);
    }

    // ---- ldmatrix lane addressing (byte offsets within a stage) ----
    // A x4: lanes 0-15 -> rows (wm+mt*16+lane&15), chunk c0; lanes 16-31 same rows, chunk c1
    int a_off[4], a_sw[4];
#pragma unroll
    for (int mt = 0; mt < 4; mt++) {
        const int r = wm + mt * 16 + (lane & 15);
        a_off[mt] = r * 128;            // bytes (64 halves/row)
        a_sw[mt]  = r & 7;
    }
    const int a_hi = (lane >> 4) & 1;   // 0 -> c0, 1 -> c1
    // B x2: lanes 0-7 -> rows n, chunk c0; lanes 8-15 -> rows n, chunk c1 (16-31 mirror)
    int b_off[4], b_sw[4];
#pragma unroll
    for (int nt = 0; nt < 4; nt++) {
        const int n = wn + nt * 8 + (lane & 7);
        b_off[nt] = n * 128;
        b_sw[nt]  = n & 7;
    }
    const int b_hi = (lane >> 3) & 1;

    float acc[4][4][4];
#pragma unroll
    for (int mt = 0; mt < 4; mt++)
#pragma unroll
        for (int nt = 0; nt < 4; nt++)
#pragma unroll
            for (int r = 0; r < 4; r++) acc[mt][nt][r] = 0.f;

    const int T = K / BK;

    auto load_stage = [&](int s, int t) {
        __half* As = sm + s * STAGE;
        __half* Bs = As + ATILE;
        const int kt = t * BK;
#pragma unroll
        for (int p = 0; p < 4; p++) cp16(As + adst[p], aptr[p] + kt);
#pragma unroll
        for (int p = 0; p < 4; p++) cp16(Bs + adst[p], bptr[p] + kt);
        CP_COMMIT();
    };

    // prologue: stages 0,1
    load_stage(0, 0);
    load_stage(1, 1);
    asm volatile("cp.async.wait_group 1;" ::: "memory");
    __syncthreads();

    for (int t = 0; t < T; t++) {
        const int s = t % NSTG;
        if (t + 2 < T) load_stage((t + 2) % NSTG, t + 2);

        const unsigned abase = smem_b + s * (STAGE * 2);
        const unsigned bbase = abase + ATILE * 2;
#pragma unroll
        for (int kk = 0; kk < 4; kk++) {
            const int ca = 2 * kk + a_hi;
            const int cb = 2 * kk + b_hi;
            unsigned bfrag[4][2];
#pragma unroll
            for (int nt = 0; nt < 4; nt++)
                ldsm_x2(bfrag[nt], bbase + b_off[nt] + ((cb ^ b_sw[nt]) << 4));
            unsigned afrag[4][4];
#pragma unroll
            for (int mt = 0; mt < 4; mt++)
                ldsm_x4(afrag[mt], abase + a_off[mt] + ((ca ^ a_sw[mt]) << 4));
#pragma unroll
            for (int mt = 0; mt < 4; mt++)
#pragma unroll
                for (int nt = 0; nt < 4; nt++)
                    mma_f16(acc[mt][nt], afrag[mt], bfrag[nt]);
        }

        if (t + 2 < T)
            asm volatile("cp.async.wait_group 1;" ::: "memory");
        else
            asm volatile("cp.async.wait_group 0;" ::: "memory");
        __syncthreads();
    }

    // epilogue
#pragma unroll
    for (int mt = 0; mt < 4; mt++) {
        const int row = bm + wm + mt * 16 + lm;
#pragma unroll
        for (int nt = 0; nt < 4; nt++) {
            const int col = bn + wn + nt * 8 + lk * 2;
            const float2 bia = *reinterpret_cast<const float2*>(&bias[col]);
            float r0x = acc[mt][nt][0] + bia.x;
            float r0y = acc[mt][nt][1] + bia.y;
            float r1x = acc[mt][nt][2] + bia.x;
            float r1y = acc[mt][nt][3] + bia.y;
            if (RELU) {
                r0x = fmaxf(r0x, 0.f); r0y = fmaxf(r0y, 0.f);
                r1x = fmaxf(r1x, 0.f); r1y = fmaxf(r1y, 0.f);
            }
            if (HOUT) {
                __half* C = (__half*)Cv;
                *reinterpret_cast<unsigned*>(C + (size_t)row * N + col)       = pack_h2(r0x, r0y);
                *reinterpret_cast<unsigned*>(C + (size_t)(row + 8) * N + col) = pack_h2(r1x, r1y);
            } else {
                float* C = (float*)Cv;
                *reinterpret_cast<float2*>(C + (size_t)row * N + col)       = make_float2(r0x, r0y);
                *reinterpret_cast<float2*>(C + (size_t)(row + 8) * N + col) = make_float2(r1x, r1y);
            }
        }
    }
}

// ---------------- block reductions ----------------
__device__ __forceinline__ float block_sum(float v, float* red) {
#pragma unroll
    for (int o = 16; o > 0; o >>= 1) v += __shfl_xor_sync(0xffffffffu, v, o);
    const int wid = threadIdx.x >> 5, lid = threadIdx.x & 31;
    const int nw = blockDim.x >> 5;
    if (lid == 0) red[wid] = v;
    __syncthreads();
    if (wid == 0) {
        v = (lid < nw) ? red[lid] : 0.f;
#pragma unroll
        for (int o = 16; o > 0; o >>= 1) v += __shfl_xor_sync(0xffffffffu, v, o);
        if (lid == 0) red[0] = v;
    }
    __syncthreads();
    float r = red[0];
    __syncthreads();
    return r;
}

__device__ __forceinline__ float block_max(float v, float* red) {
#pragma unroll
    for (int o = 16; o > 0; o >>= 1) v = fmaxf(v, __shfl_xor_sync(0xffffffffu, v, o));
    const int wid = threadIdx.x >> 5, lid = threadIdx.x & 31;
    const int nw = blockDim.x >> 5;
    if (lid == 0) red[wid] = v;
    __syncthreads();
    if (wid == 0) {
        v = (lid < nw) ? red[lid] : -3.4e38f;
#pragma unroll
        for (int o = 16; o > 0; o >>= 1) v = fmaxf(v, __shfl_xor_sync(0xffffffffu, v, o));
        if (lid == 0) red[0] = v;
    }
    __syncthreads();
    float r = red[0];
    __syncthreads();
    return r;
}

// ---------------- qp = q @ Wq + bq ----------------
__global__ void qp_kernel(const float* __restrict__ q, const float* __restrict__ Wq,
                          const float* __restrict__ bq)
{
    __shared__ float qs[DD];
    const int j = threadIdx.x;
    qs[j] = q[j];
    __syncthreads();
    float s = bq[j];
    for (int i = 0; i < DD; i++) s += qs[i] * Wq[i * DD + j];
    g_qp[j] = s;
}

// ---------------- wk_eff ----------------
__global__ void wk_eff_kernel(const float* __restrict__ Wk, const float* __restrict__ bk)
{
    __shared__ float qs[DD];
    const int i = threadIdx.x;
    qs[i] = g_qp[i];
    __syncthreads();
    const float* wr = Wk + (size_t)i * DD;
#pragma unroll
    for (int h = 0; h < NHEAD; h++) {
        float s = 0.f;
#pragma unroll
        for (int d = 0; d < HD; d++) s += wr[h * HD + d] * qs[h * HD + d];
        g_wk_eff[i * NHEAD + h] = s;
    }
    if (i < NHEAD) {
        float s = 0.f;
        for (int d = 0; d < HD; d++) s += bk[i * HD + d] * qs[i * HD + d];
        g_bk_eff[i] = s;
    }
}

// ---------------- scores ----------------
__global__ void scores_kernel()
{
    __shared__ float wk_s[DD][NHEAD];
    __shared__ float bk_s[NHEAD];
    const int tid  = threadIdx.x;
    const int warp = tid >> 5;
    const int lane = tid & 31;

    for (int i = tid; i < DD * NHEAD; i += 256)
        (&wk_s[0][0])[i] = g_wk_eff[i];
    if (tid < NHEAD) bk_s[tid] = g_bk_eff[tid];
    __syncthreads();

    const int row0 = blockIdx.x * 128;
    for (int it = 0; it < 16; it++) {
        const int row = row0 + it * 8 + warp;
        const float* hp = g_h + (size_t)row * DD;
        float acc[NHEAD];
#pragma unroll
        for (int h = 0; h < NHEAD; h++) acc[h] = 0.f;
#pragma unroll
        for (int c = 0; c < 16; c++) {
            const int i = lane + c * 32;
            const float hv = hp[i];
#pragma unroll
            for (int h = 0; h < NHEAD; h++) acc[h] += hv * wk_s[i][h];
        }
#pragma unroll
        for (int h = 0; h < NHEAD; h++) {
#pragma unroll
            for (int o = 16; o > 0; o >>= 1)
                acc[h] += __shfl_xor_sync(0xffffffffu, acc[h], o);
        }
        if (lane < NHEAD) {
            const int b = row >> 10;
            const int l = row & (LL - 1);
            float s = (acc[lane] + bk_s[lane]) * 0.125f;
            if (!g_valid[row]) s = -1e30f;
            g_s[(b * NHEAD + lane) * LL + l] = s;
        }
    }
}

// ---------------- softmax ----------------
__global__ void softmax_kernel()
{
    const int bh = blockIdx.x;
    const int tid = threadIdx.x;
    __shared__ float red[32];
    float* sp = g_s + (size_t)bh * LL;

    float v0 = sp[tid], v1 = sp[tid + 256], v2 = sp[tid + 512], v3 = sp[tid + 768];
    float mx = fmaxf(fmaxf(v0, v1), fmaxf(v2, v3));
    mx = block_max(mx, red);
    float e0 = __expf(v0 - mx), e1 = __expf(v1 - mx);
    float e2 = __expf(v2 - mx), e3 = __expf(v3 - mx);
    float sum = block_sum(e0 + e1 + e2 + e3, red);
    const float inv = 1.f / sum;
    sp[tid] = e0 * inv; sp[tid + 256] = e1 * inv;
    sp[tid + 512] = e2 * inv; sp[tid + 768] = e3 * inv;
}

// ---------------- hbar partials: grid (BB, 4) ----------------
__global__ void __launch_bounds__(512)
hbar_kernel()
{
    const int b  = blockIdx.x;
    const int ch = blockIdx.y;
    const int d  = threadIdx.x;
    __shared__ float a_s[NHEAD][256];

    for (int i = d; i < NHEAD * 256; i += 512) {
        const int h = i >> 8, l = i & 255;
        a_s[h][l] = g_s[(size_t)(b * NHEAD + h) * LL + ch * 256 + l];
    }
    __syncthreads();

    float acc[NHEAD];
#pragma unroll
    for (int h = 0; h < NHEAD; h++) acc[h] = 0.f;

    const float* hp = g_h + ((size_t)b * LL + ch * 256) * DD + d;
#pragma unroll 4
    for (int l = 0; l < 256; l++) {
        const float hv = hp[(size_t)l * DD];
#pragma unroll
        for (int h = 0; h < NHEAD; h++) acc[h] += a_s[h][l] * hv;
    }
#pragma unroll
    for (int h = 0; h < NHEAD; h++)
        g_hbarp[(((size_t)ch * BB + b) * NHEAD + h) * DD + d] = acc[h];
}

// ---------------- ctx ----------------
__global__ void ctx_kernel(const float* __restrict__ Wv, const float* __restrict__ bv)
{
    const int b = blockIdx.x;
    const int j = threadIdx.x;
    __shared__ float hb[NHEAD][DD];
    for (int i = j; i < NHEAD * DD; i += 512) {
        float s = 0.f;
#pragma unroll
        for (int c = 0; c < 4; c++)
            s += g_hbarp[((size_t)c * BB + b) * NHEAD * DD + i];
        (&hb[0][0])[i] = s;
    }
    __syncthreads();
    const int h = j >> 6;
    float s = bv[j];
    for (int i = 0; i < DD; i++) s += hb[h][i] * Wv[(size_t)i * DD + j];
    g_ctx[b * DD + j] = s;
}

// ---------------- pooled + LN ----------------
__global__ void __launch_bounds__(512)
pooled_ln_kernel(const float* __restrict__ Wo, const float* __restrict__ bo,
                 const float* __restrict__ ln_g, const float* __restrict__ ln_b)
{
    const int b = blockIdx.x;
    const int j = threadIdx.x;
    __shared__ float cx[DD];
    __shared__ float red[32];
    cx[j] = g_ctx[b * DD + j];
    __syncthreads();
    float s = bo[j];
    for (int i = 0; i < DD; i++) s += cx[i] * Wo[(size_t)i * DD + j];

    const float mu = block_sum(s, red) * (1.f / DD);
    float dv = s - mu;
    const float var = block_sum(dv * dv, red) * (1.f / DD);
    const float rstd = rsqrtf(var + 1e-5f);
    g_y[b * DD + j] = dv * rstd * ln_g[j] + ln_b[j];
}

// ---------------- head ----------------
__global__ void head1_kernel(const float* __restrict__ Wh1, const float* __restrict__ bh1,
                             const float* __restrict__ Wh2)
{
    const int b = blockIdx.x;
    const int sl = blockIdx.y;
    const int tid = threadIdx.x;
    __shared__ float y[DD];
    __shared__ float red[32];

    y[tid]       = g_y[b * DD + tid];
    y[tid + 256] = g_y[b * DD + tid + 256];
    __syncthreads();

    const int j = sl * 256 + tid;
    float t = bh1[j];
    for (int i = 0; i < DD; i++) t += y[i] * Wh1[(size_t)i * HH + j];
    float p = fmaxf(t, 0.f) * Wh2[j];
    const float tot = block_sum(p, red);
    if (tid == 0) g_hpart[b * 8 + sl] = tot;
}

__global__ void head2_kernel(const float* __restrict__ bh2, float* __restrict__ out)
{
    const int b = threadIdx.x;
    float s = bh2[0];
#pragma unroll
    for (int i = 0; i < 8; i++) s += g_hpart[b * 8 + i];
    out[b] = s;
}

// ---------------- launcher ----------------
extern "C" void kernel_launch(void* const* d_in, const int* in_sizes, int n_in,
                              void* d_out, int out_size)
{
    const int*   mut  = (const int*)d_in[0];
    const int*   offs = (const int*)d_in[1];
    const float* emb  = (const float*)d_in[2];
    const float* W1   = (const float*)d_in[3];
    const float* b1   = (const float*)d_in[4];
    const float* W2   = (const float*)d_in[5];
    const float* b2   = (const float*)d_in[6];
    const float* q    = (const float*)d_in[7];
    const float* Wq   = (const float*)d_in[8];
    const float* bq   = (const float*)d_in[9];
    const float* Wk   = (const float*)d_in[10];
    const float* bk   = (const float*)d_in[11];
    const float* Wv   = (const float*)d_in[12];
    const float* bv   = (const float*)d_in[13];
    const float* Wo   = (const float*)d_in[14];
    const float* bo   = (const float*)d_in[15];
    const float* ln_g = (const float*)d_in[16];
    const float* ln_b = (const float*)d_in[17];
    const float* Wh1  = (const float*)d_in[18];
    const float* bh1  = (const float*)d_in[19];
    const float* Wh2  = (const float*)d_in[20];
    const float* bh2  = (const float*)d_in[21];
    float* out = (float*)d_out;

    void *p_zh, *p_hidh, *p_w1t, *p_w2t, *p_h;
    cudaGetSymbolAddress(&p_zh,   g_zh);
    cudaGetSymbolAddress(&p_hidh, g_hidh);
    cudaGetSymbolAddress(&p_w1t,  g_w1t);
    cudaGetSymbolAddress(&p_w2t,  g_w2t);
    cudaGetSymbolAddress(&p_h,    g_h);
    __half* zh   = (__half*)p_zh;
    __half* hidh = (__half*)p_hidh;
    __half* w1t  = (__half*)p_w1t;
    __half* w2t  = (__half*)p_w2t;
    float*  hbf  = (float*)p_h;

    cudaFuncSetAttribute(f16_gemm_kernel<true, true>,
                         cudaFuncAttributeMaxDynamicSharedMemorySize, GSMEM);
    cudaFuncSetAttribute(f16_gemm_kernel<false, false>,
                         cudaFuncAttributeMaxDynamicSharedMemorySize, GSMEM);

    // 0) weight transpose + fp16 convert
    wtrans_kernel<<<dim3(HH / 32, DD / 32), dim3(32, 8)>>>(W1, w1t, DD, HH);
    wtrans_kernel<<<dim3(DD / 32, HH / 32), dim3(32, 8)>>>(W2, w2t, HH, DD);

    // 1) token gather + mask; gathered emb -> fp16
    gather_tok_kernel<<<TOTAL / 256, 256>>>(mut, offs);
    zh_kernel<<<(TOTAL * 64) / 256, 256>>>(emb);

    // 2) hidh = f16(relu(zh @ W1 + b1))   [65536 x 2048], K=512
    f16_gemm_kernel<true, true><<<dim3(HH / 128, TOTAL / 128), 256, GSMEM>>>(
        zh, w1t, b1, hidh, HH, DD);

    // 3) h = hidh @ W2 + b2 (fp32 out)    [65536 x 512], K=2048
    f16_gemm_kernel<false, false><<<dim3(DD / 128, TOTAL / 128), 256, GSMEM>>>(
        hidh, w2t, b2, hbf, DD, HH);

    // 4) qp, wk_eff
    qp_kernel<<<1, DD>>>(q, Wq, bq);
    wk_eff_kernel<<<1, DD>>>(Wk, bk);

    // 5) scores + softmax
    scores_kernel<<<TOTAL / 128, 256>>>();
    softmax_kernel<<<BB * NHEAD, 256>>>();

    // 6) hbar partials, ctx
    hbar_kernel<<<dim3(BB, 4), 512>>>();
    ctx_kernel<<<BB, DD>>>(Wv, bv);

    // 7) pooled + LN
    pooled_ln_kernel<<<BB, DD>>>(Wo, bo, ln_g, ln_b);

    // 8) head
    head1_kernel<<<dim3(BB, 8), 256>>>(Wh1, bh1, Wh2);
    head2_kernel<<<1, BB>>>(bh2, out);
}